// round 2
// baseline (speedup 1.0000x reference)
#include <cuda_runtime.h>
#include <math.h>

#define NNODES 100000
#define NEDGES 1600000
#define DH     128
#define DOUT   40
#define BNEPS  1e-5f

// -------------------- scratch (static device globals; no runtime alloc) ----
__device__ __align__(16) float g_h[(size_t)NNODES * DH];   // transformed features h = A@W
__device__ __align__(16) float g_a[(size_t)NNODES * DH];   // aggregation / activations
__device__ __align__(16) float g_dinv[NNODES];             // rsqrt(deg+1)
__device__ __align__(16) float g_bn[512];                  // [0:128) sum, [128:256) sumsq, [256:384) scale, [384:512) shift
__device__ int g_src[NEDGES];
__device__ int g_dst[NEDGES];
__device__ int g_is64;

// -------------------- small helpers ----------------------------------------
__device__ __forceinline__ void red_add_v4(float* addr, float x, float y, float z, float w) {
    asm volatile("red.global.add.v4.f32 [%0], {%1,%2,%3,%4};"
                 :: "l"(addr), "f"(x), "f"(y), "f"(z), "f"(w) : "memory");
}

// -------------------- dtype detect + edge conversion ------------------------
__global__ void k_detect(const long long* __restrict__ ei) {
    // Sample 256 int64 words within the first NEDGES words (safe for both dtypes).
    long long stride = NEDGES / 256;
    long long pos = (long long)threadIdx.x * stride;
    long long v = ei[pos];
    unsigned bad = __ballot_sync(0xffffffffu, (unsigned long long)v >= (unsigned long long)NNODES);
    __shared__ int sbad[8];
    int w = threadIdx.x >> 5;
    if ((threadIdx.x & 31) == 0) sbad[w] = (bad != 0);
    __syncthreads();
    if (threadIdx.x == 0) {
        int any = 0;
        #pragma unroll
        for (int i = 0; i < 8; i++) any |= sbad[i];
        g_is64 = any ? 0 : 1;   // if any sampled value >= N, data must be int32
    }
}

__global__ void k_convert(const void* __restrict__ ei) {
    int e = blockIdx.x * blockDim.x + threadIdx.x;
    if (e >= NEDGES) return;
    if (g_is64) {
        const long long* p = (const long long*)ei;
        g_src[e] = (int)p[e];
        g_dst[e] = (int)p[NEDGES + e];
    } else {
        const int* p = (const int*)ei;
        g_src[e] = p[e];
        g_dst[e] = p[NEDGES + e];
    }
}

// -------------------- degree -----------------------------------------------
__global__ void k_degree() {
    int e = blockIdx.x * blockDim.x + threadIdx.x;
    if (e >= NEDGES) return;
    atomicAdd(&g_dinv[g_dst[e]], 1.0f);
}

__global__ void k_dinv() {
    int i = blockIdx.x * blockDim.x + threadIdx.x;
    if (i < NNODES) g_dinv[i] = rsqrtf(g_dinv[i] + 1.0f);
}

// -------------------- generic zero -----------------------------------------
__global__ void k_zero(float4* __restrict__ p, int n4) {
    int i = blockIdx.x * blockDim.x + threadIdx.x;
    int stride = gridDim.x * blockDim.x;
    float4 z = make_float4(0.f, 0.f, 0.f, 0.f);
    for (; i < n4; i += stride) p[i] = z;
}

// -------------------- SGEMM  C[M,128] = act(A)[M,128] @ W[128,128] ----------
// Optional fused BN-apply+ReLU on A elements: a' = max(0, a*scale[k]+shift[k]).
template <bool APPLY_BN>
__global__ void __launch_bounds__(256)
k_gemm128(const float* __restrict__ A, const float* __restrict__ W,
          float* __restrict__ C,
          const float* __restrict__ scale, const float* __restrict__ shift, int M) {
    __shared__ float As[16][132];   // transposed tile (k, m), padded
    __shared__ float Bs[16][128];

    const int tid = threadIdx.x;
    const int tx = tid & 15;        // 16 col-groups of 8
    const int ty = tid >> 4;        // 16 row-groups of 8
    const int blockRow = blockIdx.x * 128;

    float acc[8][8];
    #pragma unroll
    for (int i = 0; i < 8; i++)
        #pragma unroll
        for (int j = 0; j < 8; j++) acc[i][j] = 0.f;

    for (int k0 = 0; k0 < 128; k0 += 16) {
        // ---- load A tile: 128 rows x 16 k, float4 per thread x2
        #pragma unroll
        for (int it = 0; it < 2; it++) {
            int idx = tid + it * 256;          // 0..511
            int r   = idx >> 2;                // 0..127
            int c4  = idx & 3;                 // which float4 along k
            int grow = blockRow + r;
            float4 v = make_float4(0.f, 0.f, 0.f, 0.f);
            if (grow < M) v = *(const float4*)(A + (size_t)grow * 128 + k0 + c4 * 4);
            if (APPLY_BN) {
                int c = k0 + c4 * 4;
                v.x = fmaxf(fmaf(v.x, scale[c + 0], shift[c + 0]), 0.f);
                v.y = fmaxf(fmaf(v.y, scale[c + 1], shift[c + 1]), 0.f);
                v.z = fmaxf(fmaf(v.z, scale[c + 2], shift[c + 2]), 0.f);
                v.w = fmaxf(fmaf(v.w, scale[c + 3], shift[c + 3]), 0.f);
            }
            As[c4 * 4 + 0][r] = v.x;
            As[c4 * 4 + 1][r] = v.y;
            As[c4 * 4 + 2][r] = v.z;
            As[c4 * 4 + 3][r] = v.w;
        }
        // ---- load W tile: 16 k x 128 n
        #pragma unroll
        for (int it = 0; it < 2; it++) {
            int idx = tid + it * 256;          // 0..511
            int r   = idx >> 5;                // 0..15
            int c4  = idx & 31;
            *(float4*)&Bs[r][c4 * 4] = *(const float4*)(W + (size_t)(k0 + r) * 128 + c4 * 4);
        }
        __syncthreads();

        #pragma unroll
        for (int k = 0; k < 16; k++) {
            float a[8], b[8];
            *(float4*)(a)     = *(const float4*)&As[k][ty * 8];
            *(float4*)(a + 4) = *(const float4*)&As[k][ty * 8 + 4];
            *(float4*)(b)     = *(const float4*)&Bs[k][tx * 8];
            *(float4*)(b + 4) = *(const float4*)&Bs[k][tx * 8 + 4];
            #pragma unroll
            for (int i = 0; i < 8; i++)
                #pragma unroll
                for (int j = 0; j < 8; j++)
                    acc[i][j] = fmaf(a[i], b[j], acc[i][j]);
        }
        __syncthreads();
    }

    #pragma unroll
    for (int i = 0; i < 8; i++) {
        int grow = blockRow + ty * 8 + i;
        if (grow < M) {
            *(float4*)(C + (size_t)grow * 128 + tx * 8)     = make_float4(acc[i][0], acc[i][1], acc[i][2], acc[i][3]);
            *(float4*)(C + (size_t)grow * 128 + tx * 8 + 4) = make_float4(acc[i][4], acc[i][5], acc[i][6], acc[i][7]);
        }
    }
}

// -------------------- SGEMM  C[M,40] = act(A)[M,128] @ W[128,40] ------------
template <bool APPLY_BN>
__global__ void __launch_bounds__(256)
k_gemm40(const float* __restrict__ A, const float* __restrict__ W,
         float* __restrict__ C,
         const float* __restrict__ scale, const float* __restrict__ shift, int M) {
    __shared__ float As[16][132];
    __shared__ float Bs[16][40];

    const int tid = threadIdx.x;
    const int tx = tid & 7;     // 8 col-groups of 5 -> 40 cols
    const int ty = tid >> 3;    // 32 row-groups of 4 -> 128 rows
    const int blockRow = blockIdx.x * 128;

    float acc[4][5];
    #pragma unroll
    for (int i = 0; i < 4; i++)
        #pragma unroll
        for (int j = 0; j < 5; j++) acc[i][j] = 0.f;

    for (int k0 = 0; k0 < 128; k0 += 16) {
        #pragma unroll
        for (int it = 0; it < 2; it++) {
            int idx = tid + it * 256;
            int r   = idx >> 2;
            int c4  = idx & 3;
            int grow = blockRow + r;
            float4 v = make_float4(0.f, 0.f, 0.f, 0.f);
            if (grow < M) v = *(const float4*)(A + (size_t)grow * 128 + k0 + c4 * 4);
            if (APPLY_BN) {
                int c = k0 + c4 * 4;
                v.x = fmaxf(fmaf(v.x, scale[c + 0], shift[c + 0]), 0.f);
                v.y = fmaxf(fmaf(v.y, scale[c + 1], shift[c + 1]), 0.f);
                v.z = fmaxf(fmaf(v.z, scale[c + 2], shift[c + 2]), 0.f);
                v.w = fmaxf(fmaf(v.w, scale[c + 3], shift[c + 3]), 0.f);
            }
            As[c4 * 4 + 0][r] = v.x;
            As[c4 * 4 + 1][r] = v.y;
            As[c4 * 4 + 2][r] = v.z;
            As[c4 * 4 + 3][r] = v.w;
        }
        for (int idx = tid; idx < 16 * 40; idx += 256) {
            int r = idx / 40, c = idx % 40;
            Bs[r][c] = W[(size_t)(k0 + r) * 40 + c];
        }
        __syncthreads();

        #pragma unroll
        for (int k = 0; k < 16; k++) {
            float a[4], b[5];
            *(float4*)a = *(const float4*)&As[k][ty * 4];
            #pragma unroll
            for (int j = 0; j < 5; j++) b[j] = Bs[k][tx * 5 + j];
            #pragma unroll
            for (int i = 0; i < 4; i++)
                #pragma unroll
                for (int j = 0; j < 5; j++)
                    acc[i][j] = fmaf(a[i], b[j], acc[i][j]);
        }
        __syncthreads();
    }

    #pragma unroll
    for (int i = 0; i < 4; i++) {
        int grow = blockRow + ty * 4 + i;
        if (grow < M) {
            #pragma unroll
            for (int j = 0; j < 5; j++)
                C[(size_t)grow * 40 + tx * 5 + j] = acc[i][j];
        }
    }
}

// -------------------- edge aggregation (D=128): one warp per edge -----------
__global__ void __launch_bounds__(256)
k_agg128(const float* __restrict__ h, float* __restrict__ out) {
    unsigned idx = blockIdx.x * 256u + threadIdx.x;
    unsigned e = idx >> 5;
    if (e >= NEDGES) return;
    int lane = idx & 31;
    int s = g_src[e], d = g_dst[e];
    float nrm = g_dinv[s] * g_dinv[d];
    float4 v = *(const float4*)(h + (size_t)s * 128 + lane * 4);
    red_add_v4(out + (size_t)d * 128 + lane * 4, v.x * nrm, v.y * nrm, v.z * nrm, v.w * nrm);
}

// -------------------- edge aggregation (D=40): 10 float4 per edge -----------
__global__ void __launch_bounds__(256)
k_agg40(const float* __restrict__ h, float* __restrict__ out) {
    unsigned idx = blockIdx.x * 256u + threadIdx.x;
    unsigned e = idx / 10u;
    if (e >= NEDGES) return;
    int c = idx % 10u;
    int s = g_src[e], d = g_dst[e];
    float nrm = g_dinv[s] * g_dinv[d];
    float4 v = *(const float4*)(h + (size_t)s * 40 + c * 4);
    red_add_v4(out + (size_t)d * 40 + c * 4, v.x * nrm, v.y * nrm, v.z * nrm, v.w * nrm);
}

// -------------------- self-loop + bias + BN column stats (D=128) ------------
__global__ void __launch_bounds__(128)
k_stats(float* __restrict__ out, const float* __restrict__ h, const float* __restrict__ bias) {
    int c = threadIdx.x;
    float b = bias[c];
    float s = 0.f, s2 = 0.f;
    for (int r = blockIdx.x; r < NNODES; r += gridDim.x) {
        float di = g_dinv[r];
        size_t o = (size_t)r * 128 + c;
        float v = out[o] + h[o] * (di * di) + b;
        out[o] = v;
        s += v; s2 += v * v;
    }
    atomicAdd(&g_bn[c], s);
    atomicAdd(&g_bn[128 + c], s2);
}

__global__ void k_bnfin(const float* __restrict__ g, const float* __restrict__ be) {
    int c = threadIdx.x;  // 128 threads
    float inv_n = 1.0f / (float)NNODES;
    float mean = g_bn[c] * inv_n;
    float var  = g_bn[128 + c] * inv_n - mean * mean;
    float sc = g[c] * rsqrtf(var + BNEPS);
    g_bn[256 + c] = sc;
    g_bn[384 + c] = be[c] - mean * sc;
}

// -------------------- final: self-loop + bias + log_softmax (warp/row) ------
__global__ void __launch_bounds__(256)
k_final(float* __restrict__ out, const float* __restrict__ h, const float* __restrict__ bf) {
    int warp = threadIdx.x >> 5, lane = threadIdx.x & 31;
    int r = blockIdx.x * 8 + warp;
    if (r >= NNODES) return;
    float di = g_dinv[r];
    float d2 = di * di;
    size_t base = (size_t)r * 40;
    float v0 = out[base + lane] + h[base + lane] * d2 + bf[lane];
    float v1 = -1e30f;
    if (lane < 8) v1 = out[base + 32 + lane] + h[base + 32 + lane] * d2 + bf[32 + lane];
    float m = fmaxf(v0, v1);
    #pragma unroll
    for (int off = 16; off >= 1; off >>= 1)
        m = fmaxf(m, __shfl_xor_sync(0xffffffffu, m, off));
    float s = expf(v0 - m) + ((lane < 8) ? expf(v1 - m) : 0.f);
    #pragma unroll
    for (int off = 16; off >= 1; off >>= 1)
        s += __shfl_xor_sync(0xffffffffu, s, off);
    float l = m + logf(s);
    out[base + lane] = v0 - l;
    if (lane < 8) out[base + 32 + lane] = v1 - l;
}

// ---------------------------------------------------------------------------
extern "C" void kernel_launch(void* const* d_in, const int* in_sizes, int n_in,
                              void* d_out, int out_size) {
    const float* x   = (const float*)d_in[0];
    const void*  ei  = d_in[1];
    const float* W1  = (const float*)d_in[2];
    const float* b1  = (const float*)d_in[3];
    const float* g1  = (const float*)d_in[4];
    const float* be1 = (const float*)d_in[5];
    const float* W2  = (const float*)d_in[6];
    const float* b2  = (const float*)d_in[7];
    const float* g2  = (const float*)d_in[8];
    const float* be2 = (const float*)d_in[9];
    const float* Wf  = (const float*)d_in[10];
    const float* bf  = (const float*)d_in[11];
    float* out = (float*)d_out;

    float *ph, *pa, *pd, *pbn;
    cudaGetSymbolAddress((void**)&ph, g_h);
    cudaGetSymbolAddress((void**)&pa, g_a);
    cudaGetSymbolAddress((void**)&pd, g_dinv);
    cudaGetSymbolAddress((void**)&pbn, g_bn);

    const int M = NNODES;
    const int gemmBlocks = (M + 127) / 128;          // 782
    const int edgeBlocks = (NEDGES + 255) / 256;     // 6250

    // edges + degree
    k_detect<<<1, 256>>>((const long long*)ei);
    k_convert<<<edgeBlocks, 256>>>(ei);
    k_zero<<<128, 256>>>((float4*)pd, NNODES / 4);
    k_degree<<<edgeBlocks, 256>>>();
    k_dinv<<<(NNODES + 255) / 256, 256>>>();

    // ---------------- layer 1
    k_gemm128<false><<<gemmBlocks, 256>>>(x, W1, ph, nullptr, nullptr, M);
    k_zero<<<4096, 256>>>((float4*)pa, M * 128 / 4);
    k_agg128<<<NEDGES / 8, 256>>>(ph, pa);
    k_zero<<<1, 256>>>((float4*)pbn, 64);            // zero sums (256 floats)
    k_stats<<<2048, 128>>>(pa, ph, b1);
    k_bnfin<<<1, 128>>>(g1, be1);

    // ---------------- layer 2 (BN apply + ReLU fused into GEMM A-load)
    k_gemm128<true><<<gemmBlocks, 256>>>(pa, W2, ph, pbn + 256, pbn + 384, M);
    k_zero<<<4096, 256>>>((float4*)pa, M * 128 / 4);
    k_agg128<<<NEDGES / 8, 256>>>(ph, pa);
    k_zero<<<1, 256>>>((float4*)pbn, 64);
    k_stats<<<2048, 128>>>(pa, ph, b2);
    k_bnfin<<<1, 128>>>(g2, be2);

    // ---------------- layer 3 (BN apply + ReLU fused into GEMM A-load)
    k_gemm40<true><<<gemmBlocks, 256>>>(pa, Wf, ph, pbn + 256, pbn + 384, M);
    k_zero<<<2048, 256>>>((float4*)out, M * 40 / 4);
    k_agg40<<<(NEDGES * 10 + 255) / 256, 256>>>(ph, out);
    k_final<<<(NNODES + 7) / 8, 256>>>(out, ph, bf);
}

// round 4
// speedup vs baseline: 1.4089x; 1.4089x over previous
#include <cuda_runtime.h>
#include <math.h>

#define NNODES 100000
#define NEDGES 1600000
#define DH     128
#define DOUT   40
#define BNEPS  1e-5f

// -------------------- scratch (static device globals) -----------------------
__device__ __align__(16) float g_h[(size_t)NNODES * DH];   // h' = (A@W)*dinv[row]
__device__ __align__(16) float g_a[(size_t)NNODES * DH];   // activations
__device__ __align__(16) float g_dinv[NNODES];             // rsqrt(deg+1)
__device__ __align__(16) int   g_cnt[NNODES];              // in-degree
__device__ __align__(16) int   g_off[NNODES + 1];          // CSR offsets
__device__ __align__(16) int   g_cur[NNODES];              // scatter cursors
__device__ __align__(16) int   g_csr[NEDGES];              // src ids grouped by dst
__device__ __align__(16) int   g_bsum[128];                // scan partials
__device__ __align__(16) int   g_bsumx[128];
__device__ __align__(16) float g_bn[512];                  // [0:128) sum, [128:256) sumsq, [256:384) scale, [384:512) shift
__device__ int g_is64;

// -------------------- dtype detect ------------------------------------------
__global__ void k_detect(const long long* __restrict__ ei) {
    long long stride = NEDGES / 256;
    long long pos = (long long)threadIdx.x * stride;
    long long v = ei[pos];
    unsigned bad = __ballot_sync(0xffffffffu, (unsigned long long)v >= (unsigned long long)NNODES);
    __shared__ int sbad[8];
    int w = threadIdx.x >> 5;
    if ((threadIdx.x & 31) == 0) sbad[w] = (bad != 0);
    __syncthreads();
    if (threadIdx.x == 0) {
        int any = 0;
        #pragma unroll
        for (int i = 0; i < 8; i++) any |= sbad[i];
        g_is64 = any ? 0 : 1;
    }
}

// -------------------- zero helpers ------------------------------------------
__global__ void k_zero(float4* __restrict__ p, int n4) {
    int i = blockIdx.x * blockDim.x + threadIdx.x;
    int stride = gridDim.x * blockDim.x;
    float4 z = make_float4(0.f, 0.f, 0.f, 0.f);
    for (; i < n4; i += stride) p[i] = z;
}
__global__ void k_zerobn() {
    g_bn[threadIdx.x] = 0.f;  // 256 threads: sums+sumsqs
}

// -------------------- degree ------------------------------------------------
__global__ void k_degree(const void* __restrict__ ei) {
    int e = blockIdx.x * blockDim.x + threadIdx.x;
    if (e >= NEDGES) return;
    int d;
    if (g_is64) d = (int)((const long long*)ei)[NEDGES + e];
    else        d = ((const int*)ei)[NEDGES + e];
    atomicAdd(&g_cnt[d], 1);
}

__global__ void k_dinv() {
    int i = blockIdx.x * blockDim.x + threadIdx.x;
    if (i < NNODES) g_dinv[i] = rsqrtf((float)g_cnt[i] + 1.0f);
}

// -------------------- exclusive scan (3 phases) ------------------------------
__global__ void k_scan1() {
    __shared__ int sh[1024];
    int t = threadIdx.x;
    int i = blockIdx.x * 1024 + t;
    int v = (i < NNODES) ? g_cnt[i] : 0;
    sh[t] = v;
    __syncthreads();
    for (int off = 1; off < 1024; off <<= 1) {
        int x = (t >= off) ? sh[t - off] : 0;
        __syncthreads();
        sh[t] += x;
        __syncthreads();
    }
    if (i < NNODES) g_off[i] = sh[t] - v;   // exclusive
    if (t == 1023) g_bsum[blockIdx.x] = sh[1023];
}

__global__ void k_scan2(int nblocks) {
    if (threadIdx.x == 0) {
        int run = 0;
        for (int b = 0; b < nblocks; b++) {
            int x = g_bsum[b];
            g_bsumx[b] = run;
            run += x;
        }
        g_off[NNODES] = run;
    }
}

__global__ void k_scan3() {
    int i = blockIdx.x * blockDim.x + threadIdx.x;
    if (i < NNODES) {
        int o = g_off[i] + g_bsumx[i >> 10];
        g_off[i] = o;
        g_cur[i] = o;
    }
}

// -------------------- scatter edges into CSR ---------------------------------
__global__ void k_scatter(const void* __restrict__ ei) {
    int e = blockIdx.x * blockDim.x + threadIdx.x;
    if (e >= NEDGES) return;
    int s, d;
    if (g_is64) {
        const long long* p = (const long long*)ei;
        s = (int)p[e]; d = (int)p[NEDGES + e];
    } else {
        const int* p = (const int*)ei;
        s = p[e]; d = p[NEDGES + e];
    }
    int pos = atomicAdd(&g_cur[d], 1);
    g_csr[pos] = s;
}

// -------------------- SGEMM  C[M,128] = act(A)@W * dinv[row] -----------------
template <bool APPLY_BN>
__global__ void __launch_bounds__(256)
k_gemm128(const float* __restrict__ A, const float* __restrict__ W,
          float* __restrict__ C,
          const float* __restrict__ scale, const float* __restrict__ shift, int M) {
    __shared__ float As[16][132];
    __shared__ float Bs[16][128];

    const int tid = threadIdx.x;
    const int tx = tid & 15;
    const int ty = tid >> 4;
    const int blockRow = blockIdx.x * 128;

    float acc[8][8];
    #pragma unroll
    for (int i = 0; i < 8; i++)
        #pragma unroll
        for (int j = 0; j < 8; j++) acc[i][j] = 0.f;

    for (int k0 = 0; k0 < 128; k0 += 16) {
        #pragma unroll
        for (int it = 0; it < 2; it++) {
            int idx = tid + it * 256;
            int r   = idx >> 2;
            int c4  = idx & 3;
            int grow = blockRow + r;
            float4 v = make_float4(0.f, 0.f, 0.f, 0.f);
            if (grow < M) v = *(const float4*)(A + (size_t)grow * 128 + k0 + c4 * 4);
            if (APPLY_BN) {
                int c = k0 + c4 * 4;
                v.x = fmaxf(fmaf(v.x, scale[c + 0], shift[c + 0]), 0.f);
                v.y = fmaxf(fmaf(v.y, scale[c + 1], shift[c + 1]), 0.f);
                v.z = fmaxf(fmaf(v.z, scale[c + 2], shift[c + 2]), 0.f);
                v.w = fmaxf(fmaf(v.w, scale[c + 3], shift[c + 3]), 0.f);
            }
            As[c4 * 4 + 0][r] = v.x;
            As[c4 * 4 + 1][r] = v.y;
            As[c4 * 4 + 2][r] = v.z;
            As[c4 * 4 + 3][r] = v.w;
        }
        #pragma unroll
        for (int it = 0; it < 2; it++) {
            int idx = tid + it * 256;
            int r   = idx >> 5;
            int c4  = idx & 31;
            *(float4*)&Bs[r][c4 * 4] = *(const float4*)(W + (size_t)(k0 + r) * 128 + c4 * 4);
        }
        __syncthreads();

        #pragma unroll
        for (int k = 0; k < 16; k++) {
            float a[8], b[8];
            *(float4*)(a)     = *(const float4*)&As[k][ty * 8];
            *(float4*)(a + 4) = *(const float4*)&As[k][ty * 8 + 4];
            *(float4*)(b)     = *(const float4*)&Bs[k][tx * 8];
            *(float4*)(b + 4) = *(const float4*)&Bs[k][tx * 8 + 4];
            #pragma unroll
            for (int i = 0; i < 8; i++)
                #pragma unroll
                for (int j = 0; j < 8; j++)
                    acc[i][j] = fmaf(a[i], b[j], acc[i][j]);
        }
        __syncthreads();
    }

    #pragma unroll
    for (int i = 0; i < 8; i++) {
        int grow = blockRow + ty * 8 + i;
        if (grow < M) {
            float di = g_dinv[grow];
            *(float4*)(C + (size_t)grow * 128 + tx * 8)     = make_float4(acc[i][0]*di, acc[i][1]*di, acc[i][2]*di, acc[i][3]*di);
            *(float4*)(C + (size_t)grow * 128 + tx * 8 + 4) = make_float4(acc[i][4]*di, acc[i][5]*di, acc[i][6]*di, acc[i][7]*di);
        }
    }
}

// -------------------- SGEMM  C[M,40] = act(A)@W * dinv[row] ------------------
template <bool APPLY_BN>
__global__ void __launch_bounds__(256)
k_gemm40(const float* __restrict__ A, const float* __restrict__ W,
         float* __restrict__ C,
         const float* __restrict__ scale, const float* __restrict__ shift, int M) {
    __shared__ float As[16][132];
    __shared__ float Bs[16][40];

    const int tid = threadIdx.x;
    const int tx = tid & 7;
    const int ty = tid >> 3;
    const int blockRow = blockIdx.x * 128;

    float acc[4][5];
    #pragma unroll
    for (int i = 0; i < 4; i++)
        #pragma unroll
        for (int j = 0; j < 5; j++) acc[i][j] = 0.f;

    for (int k0 = 0; k0 < 128; k0 += 16) {
        #pragma unroll
        for (int it = 0; it < 2; it++) {
            int idx = tid + it * 256;
            int r   = idx >> 2;
            int c4  = idx & 3;
            int grow = blockRow + r;
            float4 v = make_float4(0.f, 0.f, 0.f, 0.f);
            if (grow < M) v = *(const float4*)(A + (size_t)grow * 128 + k0 + c4 * 4);
            if (APPLY_BN) {
                int c = k0 + c4 * 4;
                v.x = fmaxf(fmaf(v.x, scale[c + 0], shift[c + 0]), 0.f);
                v.y = fmaxf(fmaf(v.y, scale[c + 1], shift[c + 1]), 0.f);
                v.z = fmaxf(fmaf(v.z, scale[c + 2], shift[c + 2]), 0.f);
                v.w = fmaxf(fmaf(v.w, scale[c + 3], shift[c + 3]), 0.f);
            }
            As[c4 * 4 + 0][r] = v.x;
            As[c4 * 4 + 1][r] = v.y;
            As[c4 * 4 + 2][r] = v.z;
            As[c4 * 4 + 3][r] = v.w;
        }
        for (int idx = tid; idx < 16 * 40; idx += 256) {
            int r = idx / 40, c = idx % 40;
            Bs[r][c] = W[(size_t)(k0 + r) * 40 + c];
        }
        __syncthreads();

        #pragma unroll
        for (int k = 0; k < 16; k++) {
            float a[4], b[5];
            *(float4*)a = *(const float4*)&As[k][ty * 4];
            #pragma unroll
            for (int j = 0; j < 5; j++) b[j] = Bs[k][tx * 5 + j];
            #pragma unroll
            for (int i = 0; i < 4; i++)
                #pragma unroll
                for (int j = 0; j < 5; j++)
                    acc[i][j] = fmaf(a[i], b[j], acc[i][j]);
        }
        __syncthreads();
    }

    #pragma unroll
    for (int i = 0; i < 4; i++) {
        int grow = blockRow + ty * 4 + i;
        if (grow < M) {
            float di = g_dinv[grow];
            #pragma unroll
            for (int j = 0; j < 5; j++)
                C[(size_t)grow * 40 + tx * 5 + j] = acc[i][j] * di;
        }
    }
}

// -------------------- CSR aggregation D=128 + self + bias + BN stats ---------
// out[d] = dinv[d] * (sum_{s in N(d)} h'[s] + h'[d]) + bias
__global__ void __launch_bounds__(256)
k_agg128(const float* __restrict__ hp, float* __restrict__ out,
         const float* __restrict__ bias) {
    __shared__ float ssum[128];
    __shared__ float ssq[128];
    int tid  = threadIdx.x;
    int warp = tid >> 5, lane = tid & 31;
    if (tid < 128) { ssum[tid] = 0.f; ssq[tid] = 0.f; }
    __syncthreads();

    int r = blockIdx.x * 8 + warp;
    float4 v = make_float4(0.f, 0.f, 0.f, 0.f);
    bool ok = (r < NNODES);
    if (ok) {
        float4 acc = *(const float4*)(hp + (size_t)r * 128 + lane * 4);  // self
        int beg = g_off[r], end = g_off[r + 1];
        #pragma unroll 4
        for (int e = beg; e < end; e++) {
            int s = g_csr[e];
            float4 u = *(const float4*)(hp + (size_t)s * 128 + lane * 4);
            acc.x += u.x; acc.y += u.y; acc.z += u.z; acc.w += u.w;
        }
        float di = g_dinv[r];
        float4 b = *(const float4*)(bias + lane * 4);
        v.x = fmaf(acc.x, di, b.x);
        v.y = fmaf(acc.y, di, b.y);
        v.z = fmaf(acc.z, di, b.z);
        v.w = fmaf(acc.w, di, b.w);
        *(float4*)(out + (size_t)r * 128 + lane * 4) = v;
        atomicAdd(&ssum[lane * 4 + 0], v.x);
        atomicAdd(&ssum[lane * 4 + 1], v.y);
        atomicAdd(&ssum[lane * 4 + 2], v.z);
        atomicAdd(&ssum[lane * 4 + 3], v.w);
        atomicAdd(&ssq[lane * 4 + 0], v.x * v.x);
        atomicAdd(&ssq[lane * 4 + 1], v.y * v.y);
        atomicAdd(&ssq[lane * 4 + 2], v.z * v.z);
        atomicAdd(&ssq[lane * 4 + 3], v.w * v.w);
    }
    __syncthreads();
    if (tid < 128) {
        atomicAdd(&g_bn[tid], ssum[tid]);
        atomicAdd(&g_bn[128 + tid], ssq[tid]);
    }
}

__global__ void k_bnfin(const float* __restrict__ g, const float* __restrict__ be) {
    int c = threadIdx.x;  // 128 threads
    float inv_n = 1.0f / (float)NNODES;
    float mean = g_bn[c] * inv_n;
    float var  = g_bn[128 + c] * inv_n - mean * mean;
    float sc = g[c] * rsqrtf(var + BNEPS);
    g_bn[256 + c] = sc;
    g_bn[384 + c] = be[c] - mean * sc;
    g_bn[c] = 0.f;           // reset sums for next layer
    g_bn[128 + c] = 0.f;
}

// -------------------- CSR aggregation D=40 + self + bias + log_softmax -------
__global__ void __launch_bounds__(256)
k_agg40(const float* __restrict__ hp, float* __restrict__ out,
        const float* __restrict__ bf) {
    int tid  = threadIdx.x;
    int warp = tid >> 5, lane = tid & 31;
    int r = blockIdx.x * 8 + warp;
    if (r >= NNODES) return;
    bool cok = (lane < 10);   // lanes 0..9 hold the 40 columns as float4

    float4 acc = make_float4(0.f, 0.f, 0.f, 0.f);
    if (cok) acc = *(const float4*)(hp + (size_t)r * 40 + lane * 4);  // self
    int beg = g_off[r], end = g_off[r + 1];
    #pragma unroll 4
    for (int e = beg; e < end; e++) {
        int s = g_csr[e];
        if (cok) {
            float4 u = *(const float4*)(hp + (size_t)s * 40 + lane * 4);
            acc.x += u.x; acc.y += u.y; acc.z += u.z; acc.w += u.w;
        }
    }
    float di = g_dinv[r];
    float4 v = make_float4(-1e30f, -1e30f, -1e30f, -1e30f);
    if (cok) {
        float4 b = *(const float4*)(bf + lane * 4);
        v.x = fmaf(acc.x, di, b.x);
        v.y = fmaf(acc.y, di, b.y);
        v.z = fmaf(acc.z, di, b.z);
        v.w = fmaf(acc.w, di, b.w);
    }
    // log_softmax over the 40 values (lanes 0..9)
    float m = fmaxf(fmaxf(v.x, v.y), fmaxf(v.z, v.w));
    #pragma unroll
    for (int off = 16; off >= 1; off >>= 1)
        m = fmaxf(m, __shfl_xor_sync(0xffffffffu, m, off));
    float s = 0.f;
    if (cok) s = expf(v.x - m) + expf(v.y - m) + expf(v.z - m) + expf(v.w - m);
    #pragma unroll
    for (int off = 16; off >= 1; off >>= 1)
        s += __shfl_xor_sync(0xffffffffu, s, off);
    float l = m + logf(s);
    if (cok) {
        float4 o = make_float4(v.x - l, v.y - l, v.z - l, v.w - l);
        *(float4*)(out + (size_t)r * 40 + lane * 4) = o;
    }
}

// ---------------------------------------------------------------------------
extern "C" void kernel_launch(void* const* d_in, const int* in_sizes, int n_in,
                              void* d_out, int out_size) {
    const float* x   = (const float*)d_in[0];
    const void*  ei  = d_in[1];
    const float* W1  = (const float*)d_in[2];
    const float* b1  = (const float*)d_in[3];
    const float* g1  = (const float*)d_in[4];
    const float* be1 = (const float*)d_in[5];
    const float* W2  = (const float*)d_in[6];
    const float* b2  = (const float*)d_in[7];
    const float* g2  = (const float*)d_in[8];
    const float* be2 = (const float*)d_in[9];
    const float* Wf  = (const float*)d_in[10];
    const float* bf  = (const float*)d_in[11];
    float* out = (float*)d_out;

    float *ph, *pa, *pbn;
    int   *pcnt;
    cudaGetSymbolAddress((void**)&ph, g_h);
    cudaGetSymbolAddress((void**)&pa, g_a);
    cudaGetSymbolAddress((void**)&pbn, g_bn);
    cudaGetSymbolAddress((void**)&pcnt, g_cnt);

    const int M = NNODES;
    const int gemmBlocks = (M + 127) / 128;          // 782
    const int edgeBlocks = (NEDGES + 255) / 256;     // 6250
    const int nodeBlocks = (NNODES + 7) / 8;         // 12500
    const int scanBlocks = (NNODES + 1023) / 1024;   // 98

    // ---- setup: CSR build ----
    k_detect<<<1, 256>>>((const long long*)ei);
    k_zero<<<64, 256>>>((float4*)pcnt, NNODES / 4);
    k_zerobn<<<1, 256>>>();
    k_degree<<<edgeBlocks, 256>>>(ei);
    k_dinv<<<(NNODES + 255) / 256, 256>>>();
    k_scan1<<<scanBlocks, 1024>>>();
    k_scan2<<<1, 32>>>(scanBlocks);
    k_scan3<<<(NNODES + 255) / 256, 256>>>();
    k_scatter<<<edgeBlocks, 256>>>(ei);

    // ---- layer 1 ----
    k_gemm128<false><<<gemmBlocks, 256>>>(x, W1, ph, nullptr, nullptr, M);
    k_agg128<<<nodeBlocks, 256>>>(ph, pa, b1);
    k_bnfin<<<1, 128>>>(g1, be1);

    // ---- layer 2 ----
    k_gemm128<true><<<gemmBlocks, 256>>>(pa, W2, ph, pbn + 256, pbn + 384, M);
    k_agg128<<<nodeBlocks, 256>>>(ph, pa, b2);
    k_bnfin<<<1, 128>>>(g2, be2);

    // ---- layer 3 ----
    k_gemm40<true><<<gemmBlocks, 256>>>(pa, Wf, ph, pbn + 256, pbn + 384, M);
    k_agg40<<<nodeBlocks, 256>>>(ph, out, bf);
}

// round 5
// speedup vs baseline: 1.4443x; 1.0251x over previous
#include <cuda_runtime.h>
#include <mma.h>
#include <math.h>

using namespace nvcuda;

#define NNODES 100000
#define NEDGES 1600000
#define DH     128
#define DOUT   40
#define BNEPS  1e-5f
#define NPAD   (NNODES + 128)   // padding rows so full-tile wmma stores never escape the buffer

// -------------------- scratch (static device globals) -----------------------
__device__ __align__(16) float g_h[(size_t)NPAD * DH];     // h = act(A)@W  (unscaled)
__device__ __align__(16) float g_a[(size_t)NPAD * DH];     // activations
__device__ __align__(16) float g_dinv[NNODES];             // rsqrt(deg+1)
__device__ __align__(16) int   g_cnt[NNODES];              // in-degree
__device__ __align__(16) int   g_off[NNODES + 1];          // CSR offsets
__device__ __align__(16) int   g_cur[NNODES];              // scatter cursors
__device__ __align__(16) int   g_csr[NEDGES];              // src ids grouped by dst
__device__ __align__(16) int   g_bsum[128];                // scan partials
__device__ __align__(16) int   g_bsumx[128];
__device__ __align__(16) float g_bn[512];                  // [0:128) sum, [128:256) sumsq, [256:384) scale, [384:512) shift
__device__ int g_is64;

// -------------------- dtype detect ------------------------------------------
__global__ void k_detect(const long long* __restrict__ ei) {
    long long stride = NEDGES / 256;
    long long pos = (long long)threadIdx.x * stride;
    long long v = ei[pos];
    unsigned bad = __ballot_sync(0xffffffffu, (unsigned long long)v >= (unsigned long long)NNODES);
    __shared__ int sbad[8];
    int w = threadIdx.x >> 5;
    if ((threadIdx.x & 31) == 0) sbad[w] = (bad != 0);
    __syncthreads();
    if (threadIdx.x == 0) {
        int any = 0;
        #pragma unroll
        for (int i = 0; i < 8; i++) any |= sbad[i];
        g_is64 = any ? 0 : 1;
    }
}

// -------------------- zero helpers ------------------------------------------
__global__ void k_zero(float4* __restrict__ p, int n4) {
    int i = blockIdx.x * blockDim.x + threadIdx.x;
    int stride = gridDim.x * blockDim.x;
    float4 z = make_float4(0.f, 0.f, 0.f, 0.f);
    for (; i < n4; i += stride) p[i] = z;
}
__global__ void k_zerobn() {
    g_bn[threadIdx.x] = 0.f;  // 256 threads: sums+sumsqs
}

// -------------------- degree ------------------------------------------------
__global__ void k_degree(const void* __restrict__ ei) {
    int e = blockIdx.x * blockDim.x + threadIdx.x;
    if (e >= NEDGES) return;
    int d;
    if (g_is64) d = (int)((const long long*)ei)[NEDGES + e];
    else        d = ((const int*)ei)[NEDGES + e];
    atomicAdd(&g_cnt[d], 1);
}

__global__ void k_dinv() {
    int i = blockIdx.x * blockDim.x + threadIdx.x;
    if (i < NNODES) g_dinv[i] = rsqrtf((float)g_cnt[i] + 1.0f);
}

// -------------------- exclusive scan (3 phases) ------------------------------
__global__ void k_scan1() {
    __shared__ int sh[1024];
    int t = threadIdx.x;
    int i = blockIdx.x * 1024 + t;
    int v = (i < NNODES) ? g_cnt[i] : 0;
    sh[t] = v;
    __syncthreads();
    for (int off = 1; off < 1024; off <<= 1) {
        int x = (t >= off) ? sh[t - off] : 0;
        __syncthreads();
        sh[t] += x;
        __syncthreads();
    }
    if (i < NNODES) g_off[i] = sh[t] - v;   // exclusive
    if (t == 1023) g_bsum[blockIdx.x] = sh[1023];
}

__global__ void k_scan2(int nblocks) {
    if (threadIdx.x == 0) {
        int run = 0;
        for (int b = 0; b < nblocks; b++) {
            int x = g_bsum[b];
            g_bsumx[b] = run;
            run += x;
        }
        g_off[NNODES] = run;
    }
}

__global__ void k_scan3() {
    int i = blockIdx.x * blockDim.x + threadIdx.x;
    if (i < NNODES) {
        int o = g_off[i] + g_bsumx[i >> 10];
        g_off[i] = o;
        g_cur[i] = o;
    }
}

// -------------------- scatter edges into CSR ---------------------------------
__global__ void k_scatter(const void* __restrict__ ei) {
    int e = blockIdx.x * blockDim.x + threadIdx.x;
    if (e >= NEDGES) return;
    int s, d;
    if (g_is64) {
        const long long* p = (const long long*)ei;
        s = (int)p[e]; d = (int)p[NEDGES + e];
    } else {
        const int* p = (const int*)ei;
        s = p[e]; d = p[NEDGES + e];
    }
    int pos = atomicAdd(&g_cur[d], 1);
    g_csr[pos] = s;
}

// -------------------- tf32 tensor-core GEMM  C[M,128] = act(A)@W -------------
// Block: 128x128 tile, 8 warps as 4(M) x 2(N); warp: 32x64 = 2x4 wmma tiles.
// K-tiles of 32. Optional fused BN apply + ReLU on A elements.
template <bool APPLY_BN>
__global__ void __launch_bounds__(256)
k_gemm128_tc(const float* __restrict__ A, const float* __restrict__ W,
             float* __restrict__ C,
             const float* __restrict__ scale, const float* __restrict__ shift, int M) {
    __shared__ float As[128][36];    // 128 rows x 32 k (pad 4)
    __shared__ float Bs[32][132];    // 32 k x 128 n   (pad 4)

    const int tid   = threadIdx.x;
    const int warp  = tid >> 5;
    const int warpM = warp >> 1;     // 0..3
    const int warpN = warp & 1;      // 0..1
    const int blockRow = blockIdx.x * 128;

    wmma::fragment<wmma::accumulator, 16, 16, 8, float> acc[2][4];
    #pragma unroll
    for (int i = 0; i < 2; i++)
        #pragma unroll
        for (int j = 0; j < 4; j++)
            wmma::fill_fragment(acc[i][j], 0.0f);

    for (int kt = 0; kt < 4; kt++) {
        // ---- A tile: 128 x 32 floats = 1024 float4, 4 per thread
        #pragma unroll
        for (int it = 0; it < 4; it++) {
            int idx = tid + it * 256;            // 0..1023
            int r   = idx >> 3;                  // 0..127
            int c4  = idx & 7;                   // 0..7
            int grow = blockRow + r;
            float4 v = make_float4(0.f, 0.f, 0.f, 0.f);
            if (grow < M) v = *(const float4*)(A + (size_t)grow * 128 + kt * 32 + c4 * 4);
            if (APPLY_BN) {
                int c = kt * 32 + c4 * 4;
                v.x = fmaxf(fmaf(v.x, scale[c + 0], shift[c + 0]), 0.f);
                v.y = fmaxf(fmaf(v.y, scale[c + 1], shift[c + 1]), 0.f);
                v.z = fmaxf(fmaf(v.z, scale[c + 2], shift[c + 2]), 0.f);
                v.w = fmaxf(fmaf(v.w, scale[c + 3], shift[c + 3]), 0.f);
            }
            *(float4*)&As[r][c4 * 4] = v;
        }
        // ---- B tile: 32 x 128 floats = 1024 float4
        #pragma unroll
        for (int it = 0; it < 4; it++) {
            int idx = tid + it * 256;
            int r   = idx >> 5;                  // 0..31
            int c4  = idx & 31;                  // 0..31
            *(float4*)&Bs[r][c4 * 4] = *(const float4*)(W + (size_t)(kt * 32 + r) * 128 + c4 * 4);
        }
        __syncthreads();

        #pragma unroll
        for (int ks = 0; ks < 4; ks++) {
            wmma::fragment<wmma::matrix_a, 16, 16, 8, wmma::precision::tf32, wmma::row_major> af[2];
            wmma::fragment<wmma::matrix_b, 16, 16, 8, wmma::precision::tf32, wmma::row_major> bfr[4];
            #pragma unroll
            for (int i = 0; i < 2; i++) {
                wmma::load_matrix_sync(af[i], &As[warpM * 32 + i * 16][ks * 8], 36);
                #pragma unroll
                for (int t = 0; t < af[i].num_elements; t++)
                    af[i].x[t] = wmma::__float_to_tf32(af[i].x[t]);
            }
            #pragma unroll
            for (int j = 0; j < 4; j++) {
                wmma::load_matrix_sync(bfr[j], &Bs[ks * 8][warpN * 64 + j * 16], 132);
                #pragma unroll
                for (int t = 0; t < bfr[j].num_elements; t++)
                    bfr[j].x[t] = wmma::__float_to_tf32(bfr[j].x[t]);
            }
            #pragma unroll
            for (int i = 0; i < 2; i++)
                #pragma unroll
                for (int j = 0; j < 4; j++)
                    wmma::mma_sync(acc[i][j], af[i], bfr[j], acc[i][j]);
        }
        __syncthreads();
    }

    // ---- store full tiles; overflow rows land in the NPAD padding
    #pragma unroll
    for (int i = 0; i < 2; i++) {
        int grow = blockRow + warpM * 32 + i * 16;
        #pragma unroll
        for (int j = 0; j < 4; j++) {
            int gcol = warpN * 64 + j * 16;
            wmma::store_matrix_sync(C + (size_t)grow * 128 + gcol, acc[i][j], 128, wmma::mem_row_major);
        }
    }
}

// -------------------- SGEMM  C[M,40] = act(A)@W (SIMT) -----------------------
template <bool APPLY_BN>
__global__ void __launch_bounds__(256)
k_gemm40(const float* __restrict__ A, const float* __restrict__ W,
         float* __restrict__ C,
         const float* __restrict__ scale, const float* __restrict__ shift, int M) {
    __shared__ float As[16][132];
    __shared__ float Bs[16][40];

    const int tid = threadIdx.x;
    const int tx = tid & 7;
    const int ty = tid >> 3;
    const int blockRow = blockIdx.x * 128;

    float acc[4][5];
    #pragma unroll
    for (int i = 0; i < 4; i++)
        #pragma unroll
        for (int j = 0; j < 5; j++) acc[i][j] = 0.f;

    for (int k0 = 0; k0 < 128; k0 += 16) {
        #pragma unroll
        for (int it = 0; it < 2; it++) {
            int idx = tid + it * 256;
            int r   = idx >> 2;
            int c4  = idx & 3;
            int grow = blockRow + r;
            float4 v = make_float4(0.f, 0.f, 0.f, 0.f);
            if (grow < M) v = *(const float4*)(A + (size_t)grow * 128 + k0 + c4 * 4);
            if (APPLY_BN) {
                int c = k0 + c4 * 4;
                v.x = fmaxf(fmaf(v.x, scale[c + 0], shift[c + 0]), 0.f);
                v.y = fmaxf(fmaf(v.y, scale[c + 1], shift[c + 1]), 0.f);
                v.z = fmaxf(fmaf(v.z, scale[c + 2], shift[c + 2]), 0.f);
                v.w = fmaxf(fmaf(v.w, scale[c + 3], shift[c + 3]), 0.f);
            }
            As[c4 * 4 + 0][r] = v.x;
            As[c4 * 4 + 1][r] = v.y;
            As[c4 * 4 + 2][r] = v.z;
            As[c4 * 4 + 3][r] = v.w;
        }
        for (int idx = tid; idx < 16 * 40; idx += 256) {
            int r = idx / 40, c = idx % 40;
            Bs[r][c] = W[(size_t)(k0 + r) * 40 + c];
        }
        __syncthreads();

        #pragma unroll
        for (int k = 0; k < 16; k++) {
            float a[4], b[5];
            *(float4*)a = *(const float4*)&As[k][ty * 4];
            #pragma unroll
            for (int j = 0; j < 5; j++) b[j] = Bs[k][tx * 5 + j];
            #pragma unroll
            for (int i = 0; i < 4; i++)
                #pragma unroll
                for (int j = 0; j < 5; j++)
                    acc[i][j] = fmaf(a[i], b[j], acc[i][j]);
        }
        __syncthreads();
    }

    #pragma unroll
    for (int i = 0; i < 4; i++) {
        int grow = blockRow + ty * 4 + i;
        if (grow < M) {
            #pragma unroll
            for (int j = 0; j < 5; j++)
                C[(size_t)grow * 40 + tx * 5 + j] = acc[i][j];
        }
    }
}

// -------------------- CSR aggregation D=128 + norm + bias + BN stats ---------
// out[d] = dinv[d]*( dinv[d]*h[d] + sum_s dinv[s]*h[s] ) + bias
__global__ void __launch_bounds__(256)
k_agg128(const float* __restrict__ h, float* __restrict__ out,
         const float* __restrict__ bias) {
    __shared__ float ssum[128];
    __shared__ float ssq[128];
    int tid  = threadIdx.x;
    int warp = tid >> 5, lane = tid & 31;
    if (tid < 128) { ssum[tid] = 0.f; ssq[tid] = 0.f; }
    __syncthreads();

    int r = blockIdx.x * 8 + warp;
    float4 v = make_float4(0.f, 0.f, 0.f, 0.f);
    bool ok = (r < NNODES);
    if (ok) {
        float dr = g_dinv[r];
        float4 hv = *(const float4*)(h + (size_t)r * 128 + lane * 4);   // self
        float4 acc;
        acc.x = hv.x * dr; acc.y = hv.y * dr; acc.z = hv.z * dr; acc.w = hv.w * dr;
        int beg = g_off[r], end = g_off[r + 1];
        #pragma unroll 4
        for (int e = beg; e < end; e++) {
            int s = g_csr[e];
            float ds = g_dinv[s];
            float4 u = *(const float4*)(h + (size_t)s * 128 + lane * 4);
            acc.x = fmaf(u.x, ds, acc.x);
            acc.y = fmaf(u.y, ds, acc.y);
            acc.z = fmaf(u.z, ds, acc.z);
            acc.w = fmaf(u.w, ds, acc.w);
        }
        float4 b = *(const float4*)(bias + lane * 4);
        v.x = fmaf(acc.x, dr, b.x);
        v.y = fmaf(acc.y, dr, b.y);
        v.z = fmaf(acc.z, dr, b.z);
        v.w = fmaf(acc.w, dr, b.w);
        *(float4*)(out + (size_t)r * 128 + lane * 4) = v;
        atomicAdd(&ssum[lane * 4 + 0], v.x);
        atomicAdd(&ssum[lane * 4 + 1], v.y);
        atomicAdd(&ssum[lane * 4 + 2], v.z);
        atomicAdd(&ssum[lane * 4 + 3], v.w);
        atomicAdd(&ssq[lane * 4 + 0], v.x * v.x);
        atomicAdd(&ssq[lane * 4 + 1], v.y * v.y);
        atomicAdd(&ssq[lane * 4 + 2], v.z * v.z);
        atomicAdd(&ssq[lane * 4 + 3], v.w * v.w);
    }
    __syncthreads();
    if (tid < 128) {
        atomicAdd(&g_bn[tid], ssum[tid]);
        atomicAdd(&g_bn[128 + tid], ssq[tid]);
    }
}

__global__ void k_bnfin(const float* __restrict__ g, const float* __restrict__ be) {
    int c = threadIdx.x;  // 128 threads
    float inv_n = 1.0f / (float)NNODES;
    float mean = g_bn[c] * inv_n;
    float var  = g_bn[128 + c] * inv_n - mean * mean;
    float sc = g[c] * rsqrtf(var + BNEPS);
    g_bn[256 + c] = sc;
    g_bn[384 + c] = be[c] - mean * sc;
    g_bn[c] = 0.f;           // reset sums for next layer
    g_bn[128 + c] = 0.f;
}

// -------------------- CSR aggregation D=40 + norm + bias + log_softmax -------
__global__ void __launch_bounds__(256)
k_agg40(const float* __restrict__ h, float* __restrict__ out,
        const float* __restrict__ bf) {
    int tid  = threadIdx.x;
    int warp = tid >> 5, lane = tid & 31;
    int r = blockIdx.x * 8 + warp;
    if (r >= NNODES) return;
    bool cok = (lane < 10);   // lanes 0..9 hold the 40 columns as float4

    float dr = g_dinv[r];
    float4 acc = make_float4(0.f, 0.f, 0.f, 0.f);
    if (cok) {
        float4 hv = *(const float4*)(h + (size_t)r * 40 + lane * 4);    // self
        acc.x = hv.x * dr; acc.y = hv.y * dr; acc.z = hv.z * dr; acc.w = hv.w * dr;
    }
    int beg = g_off[r], end = g_off[r + 1];
    #pragma unroll 4
    for (int e = beg; e < end; e++) {
        int s = g_csr[e];
        float ds = g_dinv[s];
        if (cok) {
            float4 u = *(const float4*)(h + (size_t)s * 40 + lane * 4);
            acc.x = fmaf(u.x, ds, acc.x);
            acc.y = fmaf(u.y, ds, acc.y);
            acc.z = fmaf(u.z, ds, acc.z);
            acc.w = fmaf(u.w, ds, acc.w);
        }
    }
    float4 v = make_float4(-1e30f, -1e30f, -1e30f, -1e30f);
    if (cok) {
        float4 b = *(const float4*)(bf + lane * 4);
        v.x = fmaf(acc.x, dr, b.x);
        v.y = fmaf(acc.y, dr, b.y);
        v.z = fmaf(acc.z, dr, b.z);
        v.w = fmaf(acc.w, dr, b.w);
    }
    // log_softmax over the 40 values (lanes 0..9)
    float m = fmaxf(fmaxf(v.x, v.y), fmaxf(v.z, v.w));
    #pragma unroll
    for (int off = 16; off >= 1; off >>= 1)
        m = fmaxf(m, __shfl_xor_sync(0xffffffffu, m, off));
    float s = 0.f;
    if (cok) s = expf(v.x - m) + expf(v.y - m) + expf(v.z - m) + expf(v.w - m);
    #pragma unroll
    for (int off = 16; off >= 1; off >>= 1)
        s += __shfl_xor_sync(0xffffffffu, s, off);
    float l = m + logf(s);
    if (cok) {
        float4 o = make_float4(v.x - l, v.y - l, v.z - l, v.w - l);
        *(float4*)(out + (size_t)r * 40 + lane * 4) = o;
    }
}

// ---------------------------------------------------------------------------
extern "C" void kernel_launch(void* const* d_in, const int* in_sizes, int n_in,
                              void* d_out, int out_size) {
    const float* x   = (const float*)d_in[0];
    const void*  ei  = d_in[1];
    const float* W1  = (const float*)d_in[2];
    const float* b1  = (const float*)d_in[3];
    const float* g1  = (const float*)d_in[4];
    const float* be1 = (const float*)d_in[5];
    const float* W2  = (const float*)d_in[6];
    const float* b2  = (const float*)d_in[7];
    const float* g2  = (const float*)d_in[8];
    const float* be2 = (const float*)d_in[9];
    const float* Wf  = (const float*)d_in[10];
    const float* bf  = (const float*)d_in[11];
    float* out = (float*)d_out;

    float *ph, *pa, *pbn;
    int   *pcnt;
    cudaGetSymbolAddress((void**)&ph, g_h);
    cudaGetSymbolAddress((void**)&pa, g_a);
    cudaGetSymbolAddress((void**)&pbn, g_bn);
    cudaGetSymbolAddress((void**)&pcnt, g_cnt);

    const int M = NNODES;
    const int gemmBlocks = (M + 127) / 128;          // 782
    const int edgeBlocks = (NEDGES + 255) / 256;     // 6250
    const int nodeBlocks = (NNODES + 7) / 8;         // 12500
    const int scanBlocks = (NNODES + 1023) / 1024;   // 98

    // ---- setup: CSR build ----
    k_detect<<<1, 256>>>((const long long*)ei);
    k_zero<<<64, 256>>>((float4*)pcnt, NNODES / 4);
    k_zerobn<<<1, 256>>>();
    k_degree<<<edgeBlocks, 256>>>(ei);
    k_dinv<<<(NNODES + 255) / 256, 256>>>();
    k_scan1<<<scanBlocks, 1024>>>();
    k_scan2<<<1, 32>>>(scanBlocks);
    k_scan3<<<(NNODES + 255) / 256, 256>>>();
    k_scatter<<<edgeBlocks, 256>>>(ei);

    // ---- layer 1 ----
    k_gemm128_tc<false><<<gemmBlocks, 256>>>(x, W1, ph, nullptr, nullptr, M);
    k_agg128<<<nodeBlocks, 256>>>(ph, pa, b1);
    k_bnfin<<<1, 128>>>(g1, be1);

    // ---- layer 2 ----
    k_gemm128_tc<true><<<gemmBlocks, 256>>>(pa, W2, ph, pbn + 256, pbn + 384, M);
    k_agg128<<<nodeBlocks, 256>>>(ph, pa, b2);
    k_bnfin<<<1, 128>>>(g2, be2);

    // ---- layer 3 ----
    k_gemm40<true><<<gemmBlocks, 256>>>(pa, Wf, ph, pbn + 256, pbn + 384, M);
    k_agg40<<<nodeBlocks, 256>>>(ph, out, bf);
}

// round 6
// speedup vs baseline: 1.5736x; 1.0895x over previous
#include <cuda_runtime.h>
#include <cuda_fp16.h>
#include <mma.h>
#include <math.h>

using namespace nvcuda;

#define NNODES 100000
#define NEDGES 1600000
#define DH     128
#define DOUT   40
#define BNEPS  1e-5f
#define NPAD   (NNODES + 128)   // padding rows so full-tile wmma stores never escape the buffer

// -------------------- scratch (static device globals) -----------------------
__device__ __align__(16) __half g_h[(size_t)NPAD * DH];    // h = act(A)@W  (fp16, gather operand)
__device__ __align__(16) float  g_a[(size_t)NPAD * DH];    // activations (fp32)
__device__ __align__(16) float  g_dinv[NNODES];            // rsqrt(deg+1)
__device__ __align__(16) int    g_cnt[NNODES];             // in-degree
__device__ __align__(16) int    g_off[NNODES + 1];         // CSR offsets
__device__ __align__(16) int    g_cur[NNODES];             // scatter cursors
__device__ __align__(16) int    g_csr[NEDGES];             // src ids grouped by dst
__device__ __align__(16) int    g_bsum[128];               // scan partials
__device__ __align__(16) int    g_bsumx[128];
__device__ __align__(16) float  g_bn[512];                 // [0:128) sum, [128:256) sumsq, [256:384) scale, [384:512) shift
__device__ int g_is64;

// -------------------- dtype detect ------------------------------------------
__global__ void k_detect(const long long* __restrict__ ei) {
    long long stride = NEDGES / 256;
    long long pos = (long long)threadIdx.x * stride;
    long long v = ei[pos];
    unsigned bad = __ballot_sync(0xffffffffu, (unsigned long long)v >= (unsigned long long)NNODES);
    __shared__ int sbad[8];
    int w = threadIdx.x >> 5;
    if ((threadIdx.x & 31) == 0) sbad[w] = (bad != 0);
    __syncthreads();
    if (threadIdx.x == 0) {
        int any = 0;
        #pragma unroll
        for (int i = 0; i < 8; i++) any |= sbad[i];
        g_is64 = any ? 0 : 1;
    }
}

// -------------------- zero helpers ------------------------------------------
__global__ void k_zero(float4* __restrict__ p, int n4) {
    int i = blockIdx.x * blockDim.x + threadIdx.x;
    int stride = gridDim.x * blockDim.x;
    float4 z = make_float4(0.f, 0.f, 0.f, 0.f);
    for (; i < n4; i += stride) p[i] = z;
}
__global__ void k_zerobn() {
    g_bn[threadIdx.x] = 0.f;  // 256 threads: sums+sumsqs
}

// -------------------- degree ------------------------------------------------
__global__ void k_degree(const void* __restrict__ ei) {
    int e = blockIdx.x * blockDim.x + threadIdx.x;
    if (e >= NEDGES) return;
    int d;
    if (g_is64) d = (int)((const long long*)ei)[NEDGES + e];
    else        d = ((const int*)ei)[NEDGES + e];
    atomicAdd(&g_cnt[d], 1);
}

__global__ void k_dinv() {
    int i = blockIdx.x * blockDim.x + threadIdx.x;
    if (i < NNODES) g_dinv[i] = rsqrtf((float)g_cnt[i] + 1.0f);
}

// -------------------- exclusive scan (3 phases) ------------------------------
__global__ void k_scan1() {
    __shared__ int sh[1024];
    int t = threadIdx.x;
    int i = blockIdx.x * 1024 + t;
    int v = (i < NNODES) ? g_cnt[i] : 0;
    sh[t] = v;
    __syncthreads();
    for (int off = 1; off < 1024; off <<= 1) {
        int x = (t >= off) ? sh[t - off] : 0;
        __syncthreads();
        sh[t] += x;
        __syncthreads();
    }
    if (i < NNODES) g_off[i] = sh[t] - v;   // exclusive
    if (t == 1023) g_bsum[blockIdx.x] = sh[1023];
}

__global__ void k_scan2(int nblocks) {
    __shared__ int sh[128];
    int t = threadIdx.x;           // 128 threads
    int v = (t < nblocks) ? g_bsum[t] : 0;
    sh[t] = v;
    __syncthreads();
    #pragma unroll
    for (int off = 1; off < 128; off <<= 1) {
        int x = (t >= off) ? sh[t - off] : 0;
        __syncthreads();
        sh[t] += x;
        __syncthreads();
    }
    if (t < nblocks) g_bsumx[t] = sh[t] - v;   // exclusive
    if (t == 127) g_off[NNODES] = sh[127];
}

__global__ void k_scan3() {
    int i = blockIdx.x * blockDim.x + threadIdx.x;
    if (i < NNODES) {
        int o = g_off[i] + g_bsumx[i >> 10];
        g_off[i] = o;
        g_cur[i] = o;
    }
}

// -------------------- scatter edges into CSR ---------------------------------
__global__ void k_scatter(const void* __restrict__ ei) {
    int e = blockIdx.x * blockDim.x + threadIdx.x;
    if (e >= NEDGES) return;
    int s, d;
    if (g_is64) {
        const long long* p = (const long long*)ei;
        s = (int)p[e]; d = (int)p[NEDGES + e];
    } else {
        const int* p = (const int*)ei;
        s = p[e]; d = p[NEDGES + e];
    }
    int pos = atomicAdd(&g_cur[d], 1);
    g_csr[pos] = s;
}

// -------------------- tf32 tensor-core GEMM  C[M,128] = act(A)@W  (fp16 out) -
// Block: 128x128 tile, 8 warps as 4(M) x 2(N); warp: 32x64 = 2x4 wmma tiles.
template <bool APPLY_BN>
__global__ void __launch_bounds__(256)
k_gemm128_tc(const float* __restrict__ A, const float* __restrict__ W,
             __half* __restrict__ C,
             const float* __restrict__ scale, const float* __restrict__ shift, int M) {
    __shared__ float As[128][36];     // 128 rows x 32 k (pad 4)
    __shared__ float Bs[32][132];     // 32 k x 128 n   (pad 4)
    __shared__ float stage[8][272];   // per-warp 16x16 staging (+pad)

    const int tid   = threadIdx.x;
    const int warp  = tid >> 5;
    const int lane  = tid & 31;
    const int warpM = warp >> 1;     // 0..3
    const int warpN = warp & 1;      // 0..1
    const int blockRow = blockIdx.x * 128;

    wmma::fragment<wmma::accumulator, 16, 16, 8, float> acc[2][4];
    #pragma unroll
    for (int i = 0; i < 2; i++)
        #pragma unroll
        for (int j = 0; j < 4; j++)
            wmma::fill_fragment(acc[i][j], 0.0f);

    for (int kt = 0; kt < 4; kt++) {
        #pragma unroll
        for (int it = 0; it < 4; it++) {
            int idx = tid + it * 256;            // 0..1023
            int r   = idx >> 3;                  // 0..127
            int c4  = idx & 7;                   // 0..7
            int grow = blockRow + r;
            float4 v = make_float4(0.f, 0.f, 0.f, 0.f);
            if (grow < M) v = *(const float4*)(A + (size_t)grow * 128 + kt * 32 + c4 * 4);
            if (APPLY_BN) {
                int c = kt * 32 + c4 * 4;
                v.x = fmaxf(fmaf(v.x, scale[c + 0], shift[c + 0]), 0.f);
                v.y = fmaxf(fmaf(v.y, scale[c + 1], shift[c + 1]), 0.f);
                v.z = fmaxf(fmaf(v.z, scale[c + 2], shift[c + 2]), 0.f);
                v.w = fmaxf(fmaf(v.w, scale[c + 3], shift[c + 3]), 0.f);
            }
            *(float4*)&As[r][c4 * 4] = v;
        }
        #pragma unroll
        for (int it = 0; it < 4; it++) {
            int idx = tid + it * 256;
            int r   = idx >> 5;                  // 0..31
            int c4  = idx & 31;                  // 0..31
            *(float4*)&Bs[r][c4 * 4] = *(const float4*)(W + (size_t)(kt * 32 + r) * 128 + c4 * 4);
        }
        __syncthreads();

        #pragma unroll
        for (int ks = 0; ks < 4; ks++) {
            wmma::fragment<wmma::matrix_a, 16, 16, 8, wmma::precision::tf32, wmma::row_major> af[2];
            wmma::fragment<wmma::matrix_b, 16, 16, 8, wmma::precision::tf32, wmma::row_major> bfr[4];
            #pragma unroll
            for (int i = 0; i < 2; i++) {
                wmma::load_matrix_sync(af[i], &As[warpM * 32 + i * 16][ks * 8], 36);
                #pragma unroll
                for (int t = 0; t < af[i].num_elements; t++)
                    af[i].x[t] = wmma::__float_to_tf32(af[i].x[t]);
            }
            #pragma unroll
            for (int j = 0; j < 4; j++) {
                wmma::load_matrix_sync(bfr[j], &Bs[ks * 8][warpN * 64 + j * 16], 132);
                #pragma unroll
                for (int t = 0; t < bfr[j].num_elements; t++)
                    bfr[j].x[t] = wmma::__float_to_tf32(bfr[j].x[t]);
            }
            #pragma unroll
            for (int i = 0; i < 2; i++)
                #pragma unroll
                for (int j = 0; j < 4; j++)
                    wmma::mma_sync(acc[i][j], af[i], bfr[j], acc[i][j]);
        }
        __syncthreads();
    }

    // ---- epilogue: fp32 acc -> fp16 C via per-warp smem staging
    const int rr = lane >> 1;            // 0..15
    const int cc = (lane & 1) * 8;       // 0 or 8
    #pragma unroll
    for (int i = 0; i < 2; i++) {
        #pragma unroll
        for (int j = 0; j < 4; j++) {
            wmma::store_matrix_sync(&stage[warp][0], acc[i][j], 16, wmma::mem_row_major);
            __syncwarp();
            const float* src = &stage[warp][rr * 16 + cc];
            __half2 hv[4];
            #pragma unroll
            for (int q = 0; q < 4; q++)
                hv[q] = __floats2half2_rn(src[q * 2], src[q * 2 + 1]);
            int grow = blockRow + warpM * 32 + i * 16 + rr;    // may land in NPAD padding
            int gcol = warpN * 64 + j * 16 + cc;
            *(float4*)(C + (size_t)grow * 128 + gcol) = *(float4*)hv;
            __syncwarp();
        }
    }
}

// -------------------- SGEMM  C[M,40] = act(A)@W (SIMT, fp32 out) -------------
template <bool APPLY_BN>
__global__ void __launch_bounds__(256)
k_gemm40(const float* __restrict__ A, const float* __restrict__ W,
         float* __restrict__ C,
         const float* __restrict__ scale, const float* __restrict__ shift, int M) {
    __shared__ float As[16][132];
    __shared__ float Bs[16][40];

    const int tid = threadIdx.x;
    const int tx = tid & 7;
    const int ty = tid >> 3;
    const int blockRow = blockIdx.x * 128;

    float acc[4][5];
    #pragma unroll
    for (int i = 0; i < 4; i++)
        #pragma unroll
        for (int j = 0; j < 5; j++) acc[i][j] = 0.f;

    for (int k0 = 0; k0 < 128; k0 += 16) {
        #pragma unroll
        for (int it = 0; it < 2; it++) {
            int idx = tid + it * 256;
            int r   = idx >> 2;
            int c4  = idx & 3;
            int grow = blockRow + r;
            float4 v = make_float4(0.f, 0.f, 0.f, 0.f);
            if (grow < M) v = *(const float4*)(A + (size_t)grow * 128 + k0 + c4 * 4);
            if (APPLY_BN) {
                int c = k0 + c4 * 4;
                v.x = fmaxf(fmaf(v.x, scale[c + 0], shift[c + 0]), 0.f);
                v.y = fmaxf(fmaf(v.y, scale[c + 1], shift[c + 1]), 0.f);
                v.z = fmaxf(fmaf(v.z, scale[c + 2], shift[c + 2]), 0.f);
                v.w = fmaxf(fmaf(v.w, scale[c + 3], shift[c + 3]), 0.f);
            }
            As[c4 * 4 + 0][r] = v.x;
            As[c4 * 4 + 1][r] = v.y;
            As[c4 * 4 + 2][r] = v.z;
            As[c4 * 4 + 3][r] = v.w;
        }
        for (int idx = tid; idx < 16 * 40; idx += 256) {
            int r = idx / 40, c = idx % 40;
            Bs[r][c] = W[(size_t)(k0 + r) * 40 + c];
        }
        __syncthreads();

        #pragma unroll
        for (int k = 0; k < 16; k++) {
            float a[4], b[5];
            *(float4*)a = *(const float4*)&As[k][ty * 4];
            #pragma unroll
            for (int j = 0; j < 5; j++) b[j] = Bs[k][tx * 5 + j];
            #pragma unroll
            for (int i = 0; i < 4; i++)
                #pragma unroll
                for (int j = 0; j < 5; j++)
                    acc[i][j] = fmaf(a[i], b[j], acc[i][j]);
        }
        __syncthreads();
    }

    #pragma unroll
    for (int i = 0; i < 4; i++) {
        int grow = blockRow + ty * 4 + i;
        if (grow < M) {
            #pragma unroll
            for (int j = 0; j < 5; j++)
                C[(size_t)grow * 40 + tx * 5 + j] = acc[i][j];
        }
    }
}

// -------------------- CSR aggregation D=128 (fp16 gathers) -------------------
// out[d] = dinv[d]*( dinv[d]*h[d] + sum_s dinv[s]*h[s] ) + bias   (+ BN stats)
__global__ void __launch_bounds__(256)
k_agg128(const __half* __restrict__ h, float* __restrict__ out,
         const float* __restrict__ bias) {
    __shared__ float ssum[128];
    __shared__ float ssq[128];
    int tid  = threadIdx.x;
    int warp = tid >> 5, lane = tid & 31;
    if (tid < 128) { ssum[tid] = 0.f; ssq[tid] = 0.f; }
    __syncthreads();

    int r = blockIdx.x * 8 + warp;
    float4 v = make_float4(0.f, 0.f, 0.f, 0.f);
    bool ok = (r < NNODES);
    if (ok) {
        const int co = lane * 4;   // this lane's 4 columns
        float dr = g_dinv[r];
        float4 acc;
        {
            uint2 raw = *(const uint2*)(h + (size_t)r * 128 + co);
            float2 f0 = __half22float2(*(__half2*)&raw.x);
            float2 f1 = __half22float2(*(__half2*)&raw.y);
            acc.x = f0.x * dr; acc.y = f0.y * dr; acc.z = f1.x * dr; acc.w = f1.y * dr;
        }
        int beg = g_off[r], end = g_off[r + 1];
        int e = beg;
        // 4-wide batched edge loop: front-batch index+dinv+feature loads for MLP
        for (; e + 4 <= end; e += 4) {
            int s0 = g_csr[e], s1 = g_csr[e + 1], s2 = g_csr[e + 2], s3 = g_csr[e + 3];
            float d0 = g_dinv[s0], d1 = g_dinv[s1], d2 = g_dinv[s2], d3 = g_dinv[s3];
            uint2 r0 = *(const uint2*)(h + (size_t)s0 * 128 + co);
            uint2 r1 = *(const uint2*)(h + (size_t)s1 * 128 + co);
            uint2 r2 = *(const uint2*)(h + (size_t)s2 * 128 + co);
            uint2 r3 = *(const uint2*)(h + (size_t)s3 * 128 + co);
            float2 a0 = __half22float2(*(__half2*)&r0.x), b0 = __half22float2(*(__half2*)&r0.y);
            float2 a1 = __half22float2(*(__half2*)&r1.x), b1 = __half22float2(*(__half2*)&r1.y);
            float2 a2 = __half22float2(*(__half2*)&r2.x), b2 = __half22float2(*(__half2*)&r2.y);
            float2 a3 = __half22float2(*(__half2*)&r3.x), b3 = __half22float2(*(__half2*)&r3.y);
            acc.x = fmaf(a0.x, d0, acc.x); acc.y = fmaf(a0.y, d0, acc.y);
            acc.z = fmaf(b0.x, d0, acc.z); acc.w = fmaf(b0.y, d0, acc.w);
            acc.x = fmaf(a1.x, d1, acc.x); acc.y = fmaf(a1.y, d1, acc.y);
            acc.z = fmaf(b1.x, d1, acc.z); acc.w = fmaf(b1.y, d1, acc.w);
            acc.x = fmaf(a2.x, d2, acc.x); acc.y = fmaf(a2.y, d2, acc.y);
            acc.z = fmaf(b2.x, d2, acc.z); acc.w = fmaf(b2.y, d2, acc.w);
            acc.x = fmaf(a3.x, d3, acc.x); acc.y = fmaf(a3.y, d3, acc.y);
            acc.z = fmaf(b3.x, d3, acc.z); acc.w = fmaf(b3.y, d3, acc.w);
        }
        for (; e < end; e++) {
            int s = g_csr[e];
            float ds = g_dinv[s];
            uint2 raw = *(const uint2*)(h + (size_t)s * 128 + co);
            float2 f0 = __half22float2(*(__half2*)&raw.x);
            float2 f1 = __half22float2(*(__half2*)&raw.y);
            acc.x = fmaf(f0.x, ds, acc.x); acc.y = fmaf(f0.y, ds, acc.y);
            acc.z = fmaf(f1.x, ds, acc.z); acc.w = fmaf(f1.y, ds, acc.w);
        }
        float4 b = *(const float4*)(bias + co);
        v.x = fmaf(acc.x, dr, b.x);
        v.y = fmaf(acc.y, dr, b.y);
        v.z = fmaf(acc.z, dr, b.z);
        v.w = fmaf(acc.w, dr, b.w);
        *(float4*)(out + (size_t)r * 128 + co) = v;
        atomicAdd(&ssum[co + 0], v.x);
        atomicAdd(&ssum[co + 1], v.y);
        atomicAdd(&ssum[co + 2], v.z);
        atomicAdd(&ssum[co + 3], v.w);
        atomicAdd(&ssq[co + 0], v.x * v.x);
        atomicAdd(&ssq[co + 1], v.y * v.y);
        atomicAdd(&ssq[co + 2], v.z * v.z);
        atomicAdd(&ssq[co + 3], v.w * v.w);
    }
    __syncthreads();
    if (tid < 128) {
        atomicAdd(&g_bn[tid], ssum[tid]);
        atomicAdd(&g_bn[128 + tid], ssq[tid]);
    }
}

__global__ void k_bnfin(const float* __restrict__ g, const float* __restrict__ be) {
    int c = threadIdx.x;  // 128 threads
    float inv_n = 1.0f / (float)NNODES;
    float mean = g_bn[c] * inv_n;
    float var  = g_bn[128 + c] * inv_n - mean * mean;
    float sc = g[c] * rsqrtf(var + BNEPS);
    g_bn[256 + c] = sc;
    g_bn[384 + c] = be[c] - mean * sc;
    g_bn[c] = 0.f;           // reset sums for next layer
    g_bn[128 + c] = 0.f;
}

// -------------------- CSR aggregation D=40 + norm + bias + log_softmax -------
__global__ void __launch_bounds__(256)
k_agg40(const float* __restrict__ h, float* __restrict__ out,
        const float* __restrict__ bf) {
    int tid  = threadIdx.x;
    int warp = tid >> 5, lane = tid & 31;
    int r = blockIdx.x * 8 + warp;
    if (r >= NNODES) return;
    bool cok = (lane < 10);   // lanes 0..9 hold the 40 columns as float4

    float dr = g_dinv[r];
    float4 acc = make_float4(0.f, 0.f, 0.f, 0.f);
    if (cok) {
        float4 hv = *(const float4*)(h + (size_t)r * 40 + lane * 4);    // self
        acc.x = hv.x * dr; acc.y = hv.y * dr; acc.z = hv.z * dr; acc.w = hv.w * dr;
    }
    int beg = g_off[r], end = g_off[r + 1];
    #pragma unroll 4
    for (int e = beg; e < end; e++) {
        int s = g_csr[e];
        float ds = g_dinv[s];
        if (cok) {
            float4 u = *(const float4*)(h + (size_t)s * 40 + lane * 4);
            acc.x = fmaf(u.x, ds, acc.x);
            acc.y = fmaf(u.y, ds, acc.y);
            acc.z = fmaf(u.z, ds, acc.z);
            acc.w = fmaf(u.w, ds, acc.w);
        }
    }
    float4 v = make_float4(-1e30f, -1e30f, -1e30f, -1e30f);
    if (cok) {
        float4 b = *(const float4*)(bf + lane * 4);
        v.x = fmaf(acc.x, dr, b.x);
        v.y = fmaf(acc.y, dr, b.y);
        v.z = fmaf(acc.z, dr, b.z);
        v.w = fmaf(acc.w, dr, b.w);
    }
    // log_softmax over the 40 values (lanes 0..9)
    float m = fmaxf(fmaxf(v.x, v.y), fmaxf(v.z, v.w));
    #pragma unroll
    for (int off = 16; off >= 1; off >>= 1)
        m = fmaxf(m, __shfl_xor_sync(0xffffffffu, m, off));
    float s = 0.f;
    if (cok) s = expf(v.x - m) + expf(v.y - m) + expf(v.z - m) + expf(v.w - m);
    #pragma unroll
    for (int off = 16; off >= 1; off >>= 1)
        s += __shfl_xor_sync(0xffffffffu, s, off);
    float l = m + logf(s);
    if (cok) {
        float4 o = make_float4(v.x - l, v.y - l, v.z - l, v.w - l);
        *(float4*)(out + (size_t)r * 40 + lane * 4) = o;
    }
}

// ---------------------------------------------------------------------------
extern "C" void kernel_launch(void* const* d_in, const int* in_sizes, int n_in,
                              void* d_out, int out_size) {
    const float* x   = (const float*)d_in[0];
    const void*  ei  = d_in[1];
    const float* W1  = (const float*)d_in[2];
    const float* b1  = (const float*)d_in[3];
    const float* g1  = (const float*)d_in[4];
    const float* be1 = (const float*)d_in[5];
    const float* W2  = (const float*)d_in[6];
    const float* b2  = (const float*)d_in[7];
    const float* g2  = (const float*)d_in[8];
    const float* be2 = (const float*)d_in[9];
    const float* Wf  = (const float*)d_in[10];
    const float* bf  = (const float*)d_in[11];
    float* out = (float*)d_out;

    __half *ph;
    float *pa, *pbn;
    int   *pcnt;
    cudaGetSymbolAddress((void**)&ph, g_h);
    cudaGetSymbolAddress((void**)&pa, g_a);
    cudaGetSymbolAddress((void**)&pbn, g_bn);
    cudaGetSymbolAddress((void**)&pcnt, g_cnt);
    float* ph40 = (float*)ph;   // alias: fp32 [NPAD,40] fits inside half [NPAD,128] buffer

    const int M = NNODES;
    const int gemmBlocks = (M + 127) / 128;          // 782
    const int edgeBlocks = (NEDGES + 255) / 256;     // 6250
    const int nodeBlocks = (NNODES + 7) / 8;         // 12500
    const int scanBlocks = (NNODES + 1023) / 1024;   // 98

    // ---- setup: CSR build ----
    k_detect<<<1, 256>>>((const long long*)ei);
    k_zero<<<64, 256>>>((float4*)pcnt, NNODES / 4);
    k_zerobn<<<1, 256>>>();
    k_degree<<<edgeBlocks, 256>>>(ei);
    k_dinv<<<(NNODES + 255) / 256, 256>>>();
    k_scan1<<<scanBlocks, 1024>>>();
    k_scan2<<<1, 128>>>(scanBlocks);
    k_scan3<<<(NNODES + 255) / 256, 256>>>();
    k_scatter<<<edgeBlocks, 256>>>(ei);

    // ---- layer 1 ----
    k_gemm128_tc<false><<<gemmBlocks, 256>>>(x, W1, ph, nullptr, nullptr, M);
    k_agg128<<<nodeBlocks, 256>>>(ph, pa, b1);
    k_bnfin<<<1, 128>>>(g1, be1);

    // ---- layer 2 ----
    k_gemm128_tc<true><<<gemmBlocks, 256>>>(pa, W2, ph, pbn + 256, pbn + 384, M);
    k_agg128<<<nodeBlocks, 256>>>(ph, pa, b2);
    k_bnfin<<<1, 128>>>(g2, be2);

    // ---- layer 3 ----
    k_gemm40<true><<<gemmBlocks, 256>>>(pa, Wf, ph40, pbn + 256, pbn + 384, M);
    k_agg40<<<nodeBlocks, 256>>>(ph40, out, bf);
}

// round 8
// speedup vs baseline: 1.8866x; 1.1989x over previous
#include <cuda_runtime.h>
#include <cuda_fp16.h>
#include <mma.h>
#include <math.h>

using namespace nvcuda;

#define NNODES 100000
#define NEDGES 1600000
#define DH     128
#define DOUT   40
#define BNEPS  1e-5f
#define NPAD   (NNODES + 128)   // padding rows so full-tile stores never escape the buffer

// -------------------- scratch (static device globals) -----------------------
__device__ __align__(16) __half g_h[(size_t)NPAD * DH];    // h = act(A)@W  (fp16, gather operand)
__device__ __align__(16) __half g_a[(size_t)NPAD * DH];    // activations (fp16, raw pre-BN)
__device__ __align__(16) float  g_dinv[NNODES];            // rsqrt(deg+1)
__device__ __align__(16) int    g_cnt[NNODES];             // in-degree
__device__ __align__(16) int    g_off[NNODES + 1];         // CSR offsets
__device__ __align__(16) int    g_cur[NNODES];             // scatter cursors
__device__ __align__(16) int    g_csr[NEDGES];             // src ids grouped by dst
__device__ __align__(16) int    g_bsum[128];               // scan partials
__device__ __align__(16) int    g_bsumx[128];
__device__ __align__(16) float  g_bn[512];                 // [0:128) sum, [128:256) sumsq, [256:384) scale, [384:512) shift
__device__ int g_is64;

// -------------------- dtype detect ------------------------------------------
__global__ void k_detect(const long long* __restrict__ ei) {
    long long stride = NEDGES / 256;
    long long pos = (long long)threadIdx.x * stride;
    long long v = ei[pos];
    // If data is really int32, a 64-bit read of two packed int32 node ids is
    // >= NNODES (or negative) with overwhelming probability.
    bool bad = ((unsigned long long)v >= (unsigned long long)NNODES);
    unsigned anybad = __ballot_sync(0xffffffffu, bad);
    __shared__ int sbad[8];
    int w = threadIdx.x >> 5;
    if ((threadIdx.x & 31) == 0) sbad[w] = (anybad != 0);
    __syncthreads();
    if (threadIdx.x == 0) {
        int any = 0;
        #pragma unroll
        for (int i = 0; i < 8; i++) any |= sbad[i];
        g_is64 = any ? 0 : 1;
    }
}

// -------------------- zero helpers ------------------------------------------
__global__ void k_zero(float4* __restrict__ p, int n4) {
    int i = blockIdx.x * blockDim.x + threadIdx.x;
    int stride = gridDim.x * blockDim.x;
    float4 z = make_float4(0.f, 0.f, 0.f, 0.f);
    for (; i < n4; i += stride) p[i] = z;
}
__global__ void k_zerobn() {
    g_bn[threadIdx.x] = 0.f;  // 256 threads: sums+sumsqs
}

// -------------------- degree (2 edges per thread, vector loads) --------------
__global__ void k_degree(const void* __restrict__ ei) {
    int t = blockIdx.x * blockDim.x + threadIdx.x;
    int e = t * 2;
    if (e >= NEDGES) return;
    int d0, d1;
    if (g_is64) {
        longlong2 p = *(const longlong2*)((const long long*)ei + NEDGES + e);
        d0 = (int)p.x; d1 = (int)p.y;
    } else {
        int2 p = *(const int2*)((const int*)ei + NEDGES + e);
        d0 = p.x; d1 = p.y;
    }
    atomicAdd(&g_cnt[d0], 1);
    atomicAdd(&g_cnt[d1], 1);
}

__global__ void k_dinv() {
    int i = blockIdx.x * blockDim.x + threadIdx.x;
    if (i < NNODES) g_dinv[i] = rsqrtf((float)g_cnt[i] + 1.0f);
}

// -------------------- exclusive scan (3 phases) ------------------------------
__global__ void k_scan1() {
    __shared__ int sh[1024];
    int t = threadIdx.x;
    int i = blockIdx.x * 1024 + t;
    int v = (i < NNODES) ? g_cnt[i] : 0;
    sh[t] = v;
    __syncthreads();
    for (int off = 1; off < 1024; off <<= 1) {
        int x = (t >= off) ? sh[t - off] : 0;
        __syncthreads();
        sh[t] += x;
        __syncthreads();
    }
    if (i < NNODES) g_off[i] = sh[t] - v;   // exclusive
    if (t == 1023) g_bsum[blockIdx.x] = sh[1023];
}

__global__ void k_scan2(int nblocks) {
    __shared__ int sh[128];
    int t = threadIdx.x;           // 128 threads
    int v = (t < nblocks) ? g_bsum[t] : 0;
    sh[t] = v;
    __syncthreads();
    #pragma unroll
    for (int off = 1; off < 128; off <<= 1) {
        int x = (t >= off) ? sh[t - off] : 0;
        __syncthreads();
        sh[t] += x;
        __syncthreads();
    }
    if (t < nblocks) g_bsumx[t] = sh[t] - v;   // exclusive
    if (t == 127) g_off[NNODES] = sh[127];
}

__global__ void k_scan3() {
    int i = blockIdx.x * blockDim.x + threadIdx.x;
    if (i < NNODES) {
        int o = g_off[i] + g_bsumx[i >> 10];
        g_off[i] = o;
        g_cur[i] = o;
    }
}

// -------------------- scatter edges into CSR (2 edges per thread) ------------
__global__ void k_scatter(const void* __restrict__ ei) {
    int t = blockIdx.x * blockDim.x + threadIdx.x;
    int e = t * 2;
    if (e >= NEDGES) return;
    int s0, d0, s1, d1;
    if (g_is64) {
        const long long* p = (const long long*)ei;
        longlong2 sp = *(const longlong2*)(p + e);
        longlong2 dp = *(const longlong2*)(p + NEDGES + e);
        s0 = (int)sp.x; s1 = (int)sp.y; d0 = (int)dp.x; d1 = (int)dp.y;
    } else {
        const int* p = (const int*)ei;
        int2 sp = *(const int2*)(p + e);
        int2 dp = *(const int2*)(p + NEDGES + e);
        s0 = sp.x; s1 = sp.y; d0 = dp.x; d1 = dp.y;
    }
    g_csr[atomicAdd(&g_cur[d0], 1)] = s0;
    g_csr[atomicAdd(&g_cur[d1], 1)] = s1;
}

// -------------------- fp16 HMMA GEMM  C[M,128] = act(A)@W  (fp16 out) --------
// Block: 128x128 tile, 8 warps as 4(M) x 2(N); warp 32x64 = 2x4 m16n16k16 tiles.
// A_HALF: A is __half (raw activations); else fp32. APPLY_BN: fused BN+ReLU.
template <bool A_HALF, bool APPLY_BN>
__global__ void __launch_bounds__(256)
k_gemm128_h(const void* __restrict__ Av, const float* __restrict__ W,
            __half* __restrict__ C,
            const float* __restrict__ scale, const float* __restrict__ shift, int M) {
    __shared__ __half As[128][40];    // 128 rows x 32 k (pad 8 halves)
    __shared__ __half Bs[32][136];    // 32 k x 128 n   (pad 8)
    __shared__ float  stage[8][272];  // per-warp 16x16 fp32 staging (+pad)

    const int tid   = threadIdx.x;
    const int warp  = tid >> 5;
    const int lane  = tid & 31;
    const int warpM = warp >> 1;     // 0..3
    const int warpN = warp & 1;      // 0..1
    const int blockRow = blockIdx.x * 128;

    wmma::fragment<wmma::accumulator, 16, 16, 16, float> acc[2][4];
    #pragma unroll
    for (int i = 0; i < 2; i++)
        #pragma unroll
        for (int j = 0; j < 4; j++)
            wmma::fill_fragment(acc[i][j], 0.0f);

    for (int kt = 0; kt < 4; kt++) {
        // ---- A tile: 128 rows x 32 k -> half
        #pragma unroll
        for (int it = 0; it < 4; it++) {
            int idx = tid + it * 256;            // 0..1023
            int r   = idx >> 3;                  // 0..127
            int c4  = idx & 7;                   // 0..7 (4-elem group)
            int grow = blockRow + r;
            float4 v = make_float4(0.f, 0.f, 0.f, 0.f);
            if (grow < M) {
                if (A_HALF) {
                    uint2 raw = *(const uint2*)((const __half*)Av + (size_t)grow * 128 + kt * 32 + c4 * 4);
                    float2 f0 = __half22float2(*(__half2*)&raw.x);
                    float2 f1 = __half22float2(*(__half2*)&raw.y);
                    v = make_float4(f0.x, f0.y, f1.x, f1.y);
                } else {
                    v = *(const float4*)((const float*)Av + (size_t)grow * 128 + kt * 32 + c4 * 4);
                }
            }
            if (APPLY_BN) {
                int c = kt * 32 + c4 * 4;
                v.x = fmaxf(fmaf(v.x, scale[c + 0], shift[c + 0]), 0.f);
                v.y = fmaxf(fmaf(v.y, scale[c + 1], shift[c + 1]), 0.f);
                v.z = fmaxf(fmaf(v.z, scale[c + 2], shift[c + 2]), 0.f);
                v.w = fmaxf(fmaf(v.w, scale[c + 3], shift[c + 3]), 0.f);
            }
            __half2 h0 = __floats2half2_rn(v.x, v.y);
            __half2 h1 = __floats2half2_rn(v.z, v.w);
            uint2 packed; packed.x = *(unsigned*)&h0; packed.y = *(unsigned*)&h1;
            *(uint2*)&As[r][c4 * 4] = packed;
        }
        // ---- B tile: 32 k x 128 n -> half
        #pragma unroll
        for (int it = 0; it < 4; it++) {
            int idx = tid + it * 256;            // 0..1023
            int r   = idx >> 5;                  // 0..31
            int c4  = idx & 31;                  // 0..31
            float4 v = *(const float4*)(W + (size_t)(kt * 32 + r) * 128 + c4 * 4);
            __half2 h0 = __floats2half2_rn(v.x, v.y);
            __half2 h1 = __floats2half2_rn(v.z, v.w);
            uint2 packed; packed.x = *(unsigned*)&h0; packed.y = *(unsigned*)&h1;
            *(uint2*)&Bs[r][c4 * 4] = packed;
        }
        __syncthreads();

        #pragma unroll
        for (int ks = 0; ks < 2; ks++) {
            wmma::fragment<wmma::matrix_a, 16, 16, 16, __half, wmma::row_major> af[2];
            wmma::fragment<wmma::matrix_b, 16, 16, 16, __half, wmma::row_major> bfr[4];
            #pragma unroll
            for (int i = 0; i < 2; i++)
                wmma::load_matrix_sync(af[i], &As[warpM * 32 + i * 16][ks * 16], 40);
            #pragma unroll
            for (int j = 0; j < 4; j++)
                wmma::load_matrix_sync(bfr[j], &Bs[ks * 16][warpN * 64 + j * 16], 136);
            #pragma unroll
            for (int i = 0; i < 2; i++)
                #pragma unroll
                for (int j = 0; j < 4; j++)
                    wmma::mma_sync(acc[i][j], af[i], bfr[j], acc[i][j]);
        }
        __syncthreads();
    }

    // ---- epilogue: fp32 acc -> fp16 C via per-warp smem staging
    const int rr = lane >> 1;            // 0..15
    const int cc = (lane & 1) * 8;       // 0 or 8
    #pragma unroll
    for (int i = 0; i < 2; i++) {
        #pragma unroll
        for (int j = 0; j < 4; j++) {
            wmma::store_matrix_sync(&stage[warp][0], acc[i][j], 16, wmma::mem_row_major);
            __syncwarp();
            const float* src = &stage[warp][rr * 16 + cc];
            __half2 hv[4];
            #pragma unroll
            for (int q = 0; q < 4; q++)
                hv[q] = __floats2half2_rn(src[q * 2], src[q * 2 + 1]);
            int grow = blockRow + warpM * 32 + i * 16 + rr;    // may land in NPAD padding
            int gcol = warpN * 64 + j * 16 + cc;
            *(float4*)(C + (size_t)grow * 128 + gcol) = *(float4*)hv;
            __syncwarp();
        }
    }
}

// -------------------- SGEMM  C[M,40] = act(A)@W (A fp16, fp32 out) -----------
__global__ void __launch_bounds__(256)
k_gemm40(const __half* __restrict__ A, const float* __restrict__ W,
         float* __restrict__ C,
         const float* __restrict__ scale, const float* __restrict__ shift, int M) {
    __shared__ float As[16][132];
    __shared__ float Bs[16][40];

    const int tid = threadIdx.x;
    const int tx = tid & 7;
    const int ty = tid >> 3;
    const int blockRow = blockIdx.x * 128;

    float acc[4][5];
    #pragma unroll
    for (int i = 0; i < 4; i++)
        #pragma unroll
        for (int j = 0; j < 5; j++) acc[i][j] = 0.f;

    for (int k0 = 0; k0 < 128; k0 += 16) {
        #pragma unroll
        for (int it = 0; it < 2; it++) {
            int idx = tid + it * 256;
            int r   = idx >> 2;
            int c4  = idx & 3;
            int grow = blockRow + r;
            float4 v = make_float4(0.f, 0.f, 0.f, 0.f);
            if (grow < M) {
                uint2 raw = *(const uint2*)(A + (size_t)grow * 128 + k0 + c4 * 4);
                float2 f0 = __half22float2(*(__half2*)&raw.x);
                float2 f1 = __half22float2(*(__half2*)&raw.y);
                v = make_float4(f0.x, f0.y, f1.x, f1.y);
            }
            int c = k0 + c4 * 4;
            v.x = fmaxf(fmaf(v.x, scale[c + 0], shift[c + 0]), 0.f);
            v.y = fmaxf(fmaf(v.y, scale[c + 1], shift[c + 1]), 0.f);
            v.z = fmaxf(fmaf(v.z, scale[c + 2], shift[c + 2]), 0.f);
            v.w = fmaxf(fmaf(v.w, scale[c + 3], shift[c + 3]), 0.f);
            As[c4 * 4 + 0][r] = v.x;
            As[c4 * 4 + 1][r] = v.y;
            As[c4 * 4 + 2][r] = v.z;
            As[c4 * 4 + 3][r] = v.w;
        }
        for (int idx = tid; idx < 16 * 40; idx += 256) {
            int r = idx / 40, c = idx % 40;
            Bs[r][c] = W[(size_t)(k0 + r) * 40 + c];
        }
        __syncthreads();

        #pragma unroll
        for (int k = 0; k < 16; k++) {
            float a[4], b[5];
            *(float4*)a = *(const float4*)&As[k][ty * 4];
            #pragma unroll
            for (int j = 0; j < 5; j++) b[j] = Bs[k][tx * 5 + j];
            #pragma unroll
            for (int i = 0; i < 4; i++)
                #pragma unroll
                for (int j = 0; j < 5; j++)
                    acc[i][j] = fmaf(a[i], b[j], acc[i][j]);
        }
        __syncthreads();
    }

    #pragma unroll
    for (int i = 0; i < 4; i++) {
        int grow = blockRow + ty * 4 + i;
        if (grow < M) {
            #pragma unroll
            for (int j = 0; j < 5; j++)
                C[(size_t)grow * 40 + tx * 5 + j] = acc[i][j];
        }
    }
}

// -------------------- CSR aggregation D=128 (fp16 in/out) --------------------
// out[d] = dinv[d]*( dinv[d]*h[d] + sum_s dinv[s]*h[s] ) + bias   (+ BN stats)
__global__ void __launch_bounds__(256)
k_agg128(const __half* __restrict__ h, __half* __restrict__ out,
         const float* __restrict__ bias) {
    __shared__ float ssum[128];
    __shared__ float ssq[128];
    int tid  = threadIdx.x;
    int warp = tid >> 5, lane = tid & 31;
    if (tid < 128) { ssum[tid] = 0.f; ssq[tid] = 0.f; }
    __syncthreads();

    int r = blockIdx.x * 8 + warp;
    bool ok = (r < NNODES);
    if (ok) {
        const int co = lane * 4;   // this lane's 4 columns
        float dr = g_dinv[r];
        float4 acc;
        {
            uint2 raw = *(const uint2*)(h + (size_t)r * 128 + co);
            float2 f0 = __half22float2(*(__half2*)&raw.x);
            float2 f1 = __half22float2(*(__half2*)&raw.y);
            acc.x = f0.x * dr; acc.y = f0.y * dr; acc.z = f1.x * dr; acc.w = f1.y * dr;
        }
        int beg = g_off[r], end = g_off[r + 1];
        int e = beg;
        for (; e + 4 <= end; e += 4) {
            int s0 = g_csr[e], s1 = g_csr[e + 1], s2 = g_csr[e + 2], s3 = g_csr[e + 3];
            float d0 = g_dinv[s0], d1 = g_dinv[s1], d2 = g_dinv[s2], d3 = g_dinv[s3];
            uint2 r0 = *(const uint2*)(h + (size_t)s0 * 128 + co);
            uint2 r1 = *(const uint2*)(h + (size_t)s1 * 128 + co);
            uint2 r2 = *(const uint2*)(h + (size_t)s2 * 128 + co);
            uint2 r3 = *(const uint2*)(h + (size_t)s3 * 128 + co);
            float2 a0 = __half22float2(*(__half2*)&r0.x), b0 = __half22float2(*(__half2*)&r0.y);
            float2 a1 = __half22float2(*(__half2*)&r1.x), b1 = __half22float2(*(__half2*)&r1.y);
            float2 a2 = __half22float2(*(__half2*)&r2.x), b2 = __half22float2(*(__half2*)&r2.y);
            float2 a3 = __half22float2(*(__half2*)&r3.x), b3 = __half22float2(*(__half2*)&r3.y);
            acc.x = fmaf(a0.x, d0, acc.x); acc.y = fmaf(a0.y, d0, acc.y);
            acc.z = fmaf(b0.x, d0, acc.z); acc.w = fmaf(b0.y, d0, acc.w);
            acc.x = fmaf(a1.x, d1, acc.x); acc.y = fmaf(a1.y, d1, acc.y);
            acc.z = fmaf(b1.x, d1, acc.z); acc.w = fmaf(b1.y, d1, acc.w);
            acc.x = fmaf(a2.x, d2, acc.x); acc.y = fmaf(a2.y, d2, acc.y);
            acc.z = fmaf(b2.x, d2, acc.z); acc.w = fmaf(b2.y, d2, acc.w);
            acc.x = fmaf(a3.x, d3, acc.x); acc.y = fmaf(a3.y, d3, acc.y);
            acc.z = fmaf(b3.x, d3, acc.z); acc.w = fmaf(b3.y, d3, acc.w);
        }
        for (; e < end; e++) {
            int s = g_csr[e];
            float ds = g_dinv[s];
            uint2 raw = *(const uint2*)(h + (size_t)s * 128 + co);
            float2 f0 = __half22float2(*(__half2*)&raw.x);
            float2 f1 = __half22float2(*(__half2*)&raw.y);
            acc.x = fmaf(f0.x, ds, acc.x); acc.y = fmaf(f0.y, ds, acc.y);
            acc.z = fmaf(f1.x, ds, acc.z); acc.w = fmaf(f1.y, ds, acc.w);
        }
        float4 b = *(const float4*)(bias + co);
        float4 v;
        v.x = fmaf(acc.x, dr, b.x);
        v.y = fmaf(acc.y, dr, b.y);
        v.z = fmaf(acc.z, dr, b.z);
        v.w = fmaf(acc.w, dr, b.w);
        // store activation as fp16
        __half2 h0 = __floats2half2_rn(v.x, v.y);
        __half2 h1 = __floats2half2_rn(v.z, v.w);
        uint2 packed; packed.x = *(unsigned*)&h0; packed.y = *(unsigned*)&h1;
        *(uint2*)(out + (size_t)r * 128 + co) = packed;
        // BN stats in fp32
        atomicAdd(&ssum[co + 0], v.x);
        atomicAdd(&ssum[co + 1], v.y);
        atomicAdd(&ssum[co + 2], v.z);
        atomicAdd(&ssum[co + 3], v.w);
        atomicAdd(&ssq[co + 0], v.x * v.x);
        atomicAdd(&ssq[co + 1], v.y * v.y);
        atomicAdd(&ssq[co + 2], v.z * v.z);
        atomicAdd(&ssq[co + 3], v.w * v.w);
    }
    __syncthreads();
    if (tid < 128) {
        atomicAdd(&g_bn[tid], ssum[tid]);
        atomicAdd(&g_bn[128 + tid], ssq[tid]);
    }
}

__global__ void k_bnfin(const float* __restrict__ g, const float* __restrict__ be) {
    int c = threadIdx.x;  // 128 threads
    float inv_n = 1.0f / (float)NNODES;
    float mean = g_bn[c] * inv_n;
    float var  = g_bn[128 + c] * inv_n - mean * mean;
    float sc = g[c] * rsqrtf(var + BNEPS);
    g_bn[256 + c] = sc;
    g_bn[384 + c] = be[c] - mean * sc;
    g_bn[c] = 0.f;           // reset sums for next layer
    g_bn[128 + c] = 0.f;
}

// -------------------- CSR aggregation D=40 + norm + bias + log_softmax -------
__global__ void __launch_bounds__(256)
k_agg40(const float* __restrict__ h, float* __restrict__ out,
        const float* __restrict__ bf) {
    int tid  = threadIdx.x;
    int warp = tid >> 5, lane = tid & 31;
    int r = blockIdx.x * 8 + warp;
    if (r >= NNODES) return;
    bool cok = (lane < 10);   // lanes 0..9 hold the 40 columns as float4

    float dr = g_dinv[r];
    float4 acc = make_float4(0.f, 0.f, 0.f, 0.f);
    if (cok) {
        float4 hv = *(const float4*)(h + (size_t)r * 40 + lane * 4);    // self
        acc.x = hv.x * dr; acc.y = hv.y * dr; acc.z = hv.z * dr; acc.w = hv.w * dr;
    }
    int beg = g_off[r], end = g_off[r + 1];
    #pragma unroll 4
    for (int e = beg; e < end; e++) {
        int s = g_csr[e];
        float ds = g_dinv[s];
        if (cok) {
            float4 u = *(const float4*)(h + (size_t)s * 40 + lane * 4);
            acc.x = fmaf(u.x, ds, acc.x);
            acc.y = fmaf(u.y, ds, acc.y);
            acc.z = fmaf(u.z, ds, acc.z);
            acc.w = fmaf(u.w, ds, acc.w);
        }
    }
    float4 v = make_float4(-1e30f, -1e30f, -1e30f, -1e30f);
    if (cok) {
        float4 b = *(const float4*)(bf + lane * 4);
        v.x = fmaf(acc.x, dr, b.x);
        v.y = fmaf(acc.y, dr, b.y);
        v.z = fmaf(acc.z, dr, b.z);
        v.w = fmaf(acc.w, dr, b.w);
    }
    // log_softmax over the 40 values (lanes 0..9)
    float m = fmaxf(fmaxf(v.x, v.y), fmaxf(v.z, v.w));
    #pragma unroll
    for (int off = 16; off >= 1; off >>= 1)
        m = fmaxf(m, __shfl_xor_sync(0xffffffffu, m, off));
    float s = 0.f;
    if (cok) s = expf(v.x - m) + expf(v.y - m) + expf(v.z - m) + expf(v.w - m);
    #pragma unroll
    for (int off = 16; off >= 1; off >>= 1)
        s += __shfl_xor_sync(0xffffffffu, s, off);
    float l = m + logf(s);
    if (cok) {
        float4 o = make_float4(v.x - l, v.y - l, v.z - l, v.w - l);
        *(float4*)(out + (size_t)r * 40 + lane * 4) = o;
    }
}

// ---------------------------------------------------------------------------
extern "C" void kernel_launch(void* const* d_in, const int* in_sizes, int n_in,
                              void* d_out, int out_size) {
    const float* x   = (const float*)d_in[0];
    const void*  ei  = d_in[1];
    const float* W1  = (const float*)d_in[2];
    const float* b1  = (const float*)d_in[3];
    const float* g1  = (const float*)d_in[4];
    const float* be1 = (const float*)d_in[5];
    const float* W2  = (const float*)d_in[6];
    const float* b2  = (const float*)d_in[7];
    const float* g2  = (const float*)d_in[8];
    const float* be2 = (const float*)d_in[9];
    const float* Wf  = (const float*)d_in[10];
    const float* bf  = (const float*)d_in[11];
    float* out = (float*)d_out;

    __half *ph, *pa;
    float *pbn;
    int   *pcnt;
    cudaGetSymbolAddress((void**)&ph, g_h);
    cudaGetSymbolAddress((void**)&pa, g_a);
    cudaGetSymbolAddress((void**)&pbn, g_bn);
    cudaGetSymbolAddress((void**)&pcnt, g_cnt);
    float* ph40 = (float*)ph;   // alias: fp32 [NPAD,40] fits inside half [NPAD,128] buffer

    const int M = NNODES;
    const int gemmBlocks = (M + 127) / 128;          // 782
    const int edge2Blocks = (NEDGES / 2 + 255) / 256;// 3125
    const int nodeBlocks = (NNODES + 7) / 8;         // 12500
    const int scanBlocks = (NNODES + 1023) / 1024;   // 98

    // ---- setup: CSR build ----
    k_detect<<<1, 256>>>((const long long*)ei);
    k_zero<<<64, 256>>>((float4*)pcnt, NNODES / 4);
    k_zerobn<<<1, 256>>>();
    k_degree<<<edge2Blocks, 256>>>(ei);
    k_dinv<<<(NNODES + 255) / 256, 256>>>();
    k_scan1<<<scanBlocks, 1024>>>();
    k_scan2<<<1, 128>>>(scanBlocks);
    k_scan3<<<(NNODES + 255) / 256, 256>>>();
    k_scatter<<<edge2Blocks, 256>>>(ei);

    // ---- layer 1 ----
    k_gemm128_h<false, false><<<gemmBlocks, 256>>>(x, W1, ph, nullptr, nullptr, M);
    k_agg128<<<nodeBlocks, 256>>>(ph, pa, b1);
    k_bnfin<<<1, 128>>>(g1, be1);

    // ---- layer 2 ----
    k_gemm128_h<true, true><<<gemmBlocks, 256>>>(pa, W2, ph, pbn + 256, pbn + 384, M);
    k_agg128<<<nodeBlocks, 256>>>(ph, pa, b2);
    k_bnfin<<<1, 128>>>(g2, be2);

    // ---- layer 3 ----
    k_gemm40<<<gemmBlocks, 256>>>(pa, Wf, ph40, pbn + 256, pbn + 384, M);
    k_agg40<<<nodeBlocks, 256>>>(ph40, out, bf);
}

// round 9
// speedup vs baseline: 1.8975x; 1.0058x over previous
#include <cuda_runtime.h>
#include <cuda_fp16.h>
#include <mma.h>
#include <math.h>

using namespace nvcuda;

#define NNODES 100000
#define NEDGES 1600000
#define DH     128
#define DOUT   40
#define BNEPS  1e-5f
#define NPAD   (NNODES + 128)   // padding rows so full-tile stores never escape the buffer

// -------------------- scratch (static device globals) -----------------------
__device__ __align__(16) __half g_h[(size_t)NPAD * DH];    // h' = dinv[row]*(act(A)@W), fp16 gather operand
__device__ __align__(16) __half g_a[(size_t)NPAD * DH];    // activations (fp16, raw pre-BN)
__device__ __align__(16) float  g_dinv[NNODES];            // rsqrt(deg+1)
__device__ __align__(16) int    g_cnt[NNODES];             // in-degree
__device__ __align__(16) int    g_off[NNODES + 1];         // CSR offsets
__device__ __align__(16) int    g_cur[NNODES];             // scatter cursors
__device__ __align__(16) int    g_csr[NEDGES];             // src ids grouped by dst
__device__ __align__(16) int    g_bsum[128];               // scan partials
__device__ __align__(16) int    g_bsumx[128];
__device__ __align__(16) float  g_bn[512];                 // [0:128) sum, [128:256) sumsq, [256:384) scale, [384:512) shift
__device__ int g_is64;

// -------------------- dtype detect ------------------------------------------
__global__ void k_detect(const long long* __restrict__ ei) {
    long long stride = NEDGES / 256;
    long long pos = (long long)threadIdx.x * stride;
    long long v = ei[pos];
    bool bad = ((unsigned long long)v >= (unsigned long long)NNODES);
    unsigned anybad = __ballot_sync(0xffffffffu, bad);
    __shared__ int sbad[8];
    int w = threadIdx.x >> 5;
    if ((threadIdx.x & 31) == 0) sbad[w] = (anybad != 0);
    __syncthreads();
    if (threadIdx.x == 0) {
        int any = 0;
        #pragma unroll
        for (int i = 0; i < 8; i++) any |= sbad[i];
        g_is64 = any ? 0 : 1;
    }
}

// -------------------- zero helpers ------------------------------------------
__global__ void k_zero(float4* __restrict__ p, int n4) {
    int i = blockIdx.x * blockDim.x + threadIdx.x;
    int stride = gridDim.x * blockDim.x;
    float4 z = make_float4(0.f, 0.f, 0.f, 0.f);
    for (; i < n4; i += stride) p[i] = z;
}
__global__ void k_zerobn() {
    g_bn[threadIdx.x] = 0.f;  // 256 threads: sums+sumsqs
}

// -------------------- degree (2 edges per thread, vector loads) --------------
__global__ void k_degree(const void* __restrict__ ei) {
    int t = blockIdx.x * blockDim.x + threadIdx.x;
    int e = t * 2;
    if (e >= NEDGES) return;
    int d0, d1;
    if (g_is64) {
        longlong2 p = *(const longlong2*)((const long long*)ei + NEDGES + e);
        d0 = (int)p.x; d1 = (int)p.y;
    } else {
        int2 p = *(const int2*)((const int*)ei + NEDGES + e);
        d0 = p.x; d1 = p.y;
    }
    atomicAdd(&g_cnt[d0], 1);
    atomicAdd(&g_cnt[d1], 1);
}

// -------------------- exclusive scan (3 phases; phase3 also builds dinv) -----
__global__ void k_scan1() {
    __shared__ int sh[1024];
    int t = threadIdx.x;
    int i = blockIdx.x * 1024 + t;
    int v = (i < NNODES) ? g_cnt[i] : 0;
    sh[t] = v;
    __syncthreads();
    for (int off = 1; off < 1024; off <<= 1) {
        int x = (t >= off) ? sh[t - off] : 0;
        __syncthreads();
        sh[t] += x;
        __syncthreads();
    }
    if (i < NNODES) g_off[i] = sh[t] - v;   // exclusive
    if (t == 1023) g_bsum[blockIdx.x] = sh[1023];
}

__global__ void k_scan2(int nblocks) {
    __shared__ int sh[128];
    int t = threadIdx.x;           // 128 threads
    int v = (t < nblocks) ? g_bsum[t] : 0;
    sh[t] = v;
    __syncthreads();
    #pragma unroll
    for (int off = 1; off < 128; off <<= 1) {
        int x = (t >= off) ? sh[t - off] : 0;
        __syncthreads();
        sh[t] += x;
        __syncthreads();
    }
    if (t < nblocks) g_bsumx[t] = sh[t] - v;   // exclusive
    if (t == 127) g_off[NNODES] = sh[127];
}

__global__ void k_scan3() {
    int i = blockIdx.x * blockDim.x + threadIdx.x;
    if (i < NNODES) {
        int o = g_off[i] + g_bsumx[i >> 10];
        g_off[i] = o;
        g_cur[i] = o;
        g_dinv[i] = rsqrtf((float)g_cnt[i] + 1.0f);
    }
}

// -------------------- scatter edges into CSR (2 edges per thread) ------------
__global__ void k_scatter(const void* __restrict__ ei) {
    int t = blockIdx.x * blockDim.x + threadIdx.x;
    int e = t * 2;
    if (e >= NEDGES) return;
    int s0, d0, s1, d1;
    if (g_is64) {
        const long long* p = (const long long*)ei;
        longlong2 sp = *(const longlong2*)(p + e);
        longlong2 dp = *(const longlong2*)(p + NEDGES + e);
        s0 = (int)sp.x; s1 = (int)sp.y; d0 = (int)dp.x; d1 = (int)dp.y;
    } else {
        const int* p = (const int*)ei;
        int2 sp = *(const int2*)(p + e);
        int2 dp = *(const int2*)(p + NEDGES + e);
        s0 = sp.x; s1 = sp.y; d0 = dp.x; d1 = dp.y;
    }
    g_csr[atomicAdd(&g_cur[d0], 1)] = s0;
    g_csr[atomicAdd(&g_cur[d1], 1)] = s1;
}

// -------------------- fp16 HMMA GEMM  C[M,128] = dinv[row]*(act(A)@W) --------
// Block: 128x128 tile, 8 warps as 4(M) x 2(N); warp 32x64 = 2x4 m16n16k16 tiles.
template <bool A_HALF, bool APPLY_BN>
__global__ void __launch_bounds__(256)
k_gemm128_h(const void* __restrict__ Av, const float* __restrict__ W,
            __half* __restrict__ C,
            const float* __restrict__ scale, const float* __restrict__ shift, int M) {
    __shared__ __half As[128][40];    // 128 rows x 32 k (pad 8 halves)
    __shared__ __half Bs[32][136];    // 32 k x 128 n   (pad 8)
    __shared__ float  stage[8][272];  // per-warp 16x16 fp32 staging (+pad)

    const int tid   = threadIdx.x;
    const int warp  = tid >> 5;
    const int lane  = tid & 31;
    const int warpM = warp >> 1;     // 0..3
    const int warpN = warp & 1;      // 0..1
    const int blockRow = blockIdx.x * 128;

    wmma::fragment<wmma::accumulator, 16, 16, 16, float> acc[2][4];
    #pragma unroll
    for (int i = 0; i < 2; i++)
        #pragma unroll
        for (int j = 0; j < 4; j++)
            wmma::fill_fragment(acc[i][j], 0.0f);

    for (int kt = 0; kt < 4; kt++) {
        // ---- A tile: 128 rows x 32 k -> half
        #pragma unroll
        for (int it = 0; it < 4; it++) {
            int idx = tid + it * 256;            // 0..1023
            int r   = idx >> 3;                  // 0..127
            int c4  = idx & 7;                   // 0..7 (4-elem group)
            int grow = blockRow + r;
            float4 v = make_float4(0.f, 0.f, 0.f, 0.f);
            if (grow < M) {
                if (A_HALF) {
                    uint2 raw = *(const uint2*)((const __half*)Av + (size_t)grow * 128 + kt * 32 + c4 * 4);
                    float2 f0 = __half22float2(*(__half2*)&raw.x);
                    float2 f1 = __half22float2(*(__half2*)&raw.y);
                    v = make_float4(f0.x, f0.y, f1.x, f1.y);
                } else {
                    v = *(const float4*)((const float*)Av + (size_t)grow * 128 + kt * 32 + c4 * 4);
                }
            }
            if (APPLY_BN) {
                int c = kt * 32 + c4 * 4;
                v.x = fmaxf(fmaf(v.x, scale[c + 0], shift[c + 0]), 0.f);
                v.y = fmaxf(fmaf(v.y, scale[c + 1], shift[c + 1]), 0.f);
                v.z = fmaxf(fmaf(v.z, scale[c + 2], shift[c + 2]), 0.f);
                v.w = fmaxf(fmaf(v.w, scale[c + 3], shift[c + 3]), 0.f);
            }
            __half2 h0 = __floats2half2_rn(v.x, v.y);
            __half2 h1 = __floats2half2_rn(v.z, v.w);
            uint2 packed; packed.x = *(unsigned*)&h0; packed.y = *(unsigned*)&h1;
            *(uint2*)&As[r][c4 * 4] = packed;
        }
        // ---- B tile: 32 k x 128 n -> half
        #pragma unroll
        for (int it = 0; it < 4; it++) {
            int idx = tid + it * 256;            // 0..1023
            int r   = idx >> 5;                  // 0..31
            int c4  = idx & 31;                  // 0..31
            float4 v = *(const float4*)(W + (size_t)(kt * 32 + r) * 128 + c4 * 4);
            __half2 h0 = __floats2half2_rn(v.x, v.y);
            __half2 h1 = __floats2half2_rn(v.z, v.w);
            uint2 packed; packed.x = *(unsigned*)&h0; packed.y = *(unsigned*)&h1;
            *(uint2*)&Bs[r][c4 * 4] = packed;
        }
        __syncthreads();

        #pragma unroll
        for (int ks = 0; ks < 2; ks++) {
            wmma::fragment<wmma::matrix_a, 16, 16, 16, __half, wmma::row_major> af[2];
            wmma::fragment<wmma::matrix_b, 16, 16, 16, __half, wmma::row_major> bfr[4];
            #pragma unroll
            for (int i = 0; i < 2; i++)
                wmma::load_matrix_sync(af[i], &As[warpM * 32 + i * 16][ks * 16], 40);
            #pragma unroll
            for (int j = 0; j < 4; j++)
                wmma::load_matrix_sync(bfr[j], &Bs[ks * 16][warpN * 64 + j * 16], 136);
            #pragma unroll
            for (int i = 0; i < 2; i++)
                #pragma unroll
                for (int j = 0; j < 4; j++)
                    wmma::mma_sync(acc[i][j], af[i], bfr[j], acc[i][j]);
        }
        __syncthreads();
    }

    // ---- epilogue: fp32 acc * dinv[row] -> fp16 C via per-warp smem staging
    const int rr = lane >> 1;            // 0..15
    const int cc = (lane & 1) * 8;       // 0 or 8
    #pragma unroll
    for (int i = 0; i < 2; i++) {
        int grow = blockRow + warpM * 32 + i * 16 + rr;    // may land in NPAD padding
        float di = (grow < M) ? g_dinv[grow] : 0.f;
        #pragma unroll
        for (int j = 0; j < 4; j++) {
            wmma::store_matrix_sync(&stage[warp][0], acc[i][j], 16, wmma::mem_row_major);
            __syncwarp();
            const float* src = &stage[warp][rr * 16 + cc];
            __half2 hv[4];
            #pragma unroll
            for (int q = 0; q < 4; q++)
                hv[q] = __floats2half2_rn(src[q * 2] * di, src[q * 2 + 1] * di);
            int gcol = warpN * 64 + j * 16 + cc;
            *(float4*)(C + (size_t)grow * 128 + gcol) = *(float4*)hv;
            __syncwarp();
        }
    }
}

// -------------- SGEMM  C[M,40] = dinv[row]*(act(A)@W)  (A fp16, fp16 out) ----
__global__ void __launch_bounds__(256)
k_gemm40(const __half* __restrict__ A, const float* __restrict__ W,
         __half* __restrict__ C,
         const float* __restrict__ scale, const float* __restrict__ shift, int M) {
    __shared__ float As[16][132];
    __shared__ float Bs[16][40];

    const int tid = threadIdx.x;
    const int tx = tid & 7;
    const int ty = tid >> 3;
    const int blockRow = blockIdx.x * 128;

    float acc[4][5];
    #pragma unroll
    for (int i = 0; i < 4; i++)
        #pragma unroll
        for (int j = 0; j < 5; j++) acc[i][j] = 0.f;

    for (int k0 = 0; k0 < 128; k0 += 16) {
        #pragma unroll
        for (int it = 0; it < 2; it++) {
            int idx = tid + it * 256;
            int r   = idx >> 2;
            int c4  = idx & 3;
            int grow = blockRow + r;
            float4 v = make_float4(0.f, 0.f, 0.f, 0.f);
            if (grow < M) {
                uint2 raw = *(const uint2*)(A + (size_t)grow * 128 + k0 + c4 * 4);
                float2 f0 = __half22float2(*(__half2*)&raw.x);
                float2 f1 = __half22float2(*(__half2*)&raw.y);
                v = make_float4(f0.x, f0.y, f1.x, f1.y);
            }
            int c = k0 + c4 * 4;
            v.x = fmaxf(fmaf(v.x, scale[c + 0], shift[c + 0]), 0.f);
            v.y = fmaxf(fmaf(v.y, scale[c + 1], shift[c + 1]), 0.f);
            v.z = fmaxf(fmaf(v.z, scale[c + 2], shift[c + 2]), 0.f);
            v.w = fmaxf(fmaf(v.w, scale[c + 3], shift[c + 3]), 0.f);
            As[c4 * 4 + 0][r] = v.x;
            As[c4 * 4 + 1][r] = v.y;
            As[c4 * 4 + 2][r] = v.z;
            As[c4 * 4 + 3][r] = v.w;
        }
        for (int idx = tid; idx < 16 * 40; idx += 256) {
            int r = idx / 40, c = idx % 40;
            Bs[r][c] = W[(size_t)(k0 + r) * 40 + c];
        }
        __syncthreads();

        #pragma unroll
        for (int k = 0; k < 16; k++) {
            float a[4], b[5];
            *(float4*)a = *(const float4*)&As[k][ty * 4];
            #pragma unroll
            for (int j = 0; j < 5; j++) b[j] = Bs[k][tx * 5 + j];
            #pragma unroll
            for (int i = 0; i < 4; i++)
                #pragma unroll
                for (int j = 0; j < 5; j++)
                    acc[i][j] = fmaf(a[i], b[j], acc[i][j]);
        }
        __syncthreads();
    }

    #pragma unroll
    for (int i = 0; i < 4; i++) {
        int grow = blockRow + ty * 4 + i;
        if (grow < M) {
            float di = g_dinv[grow];
            #pragma unroll
            for (int j = 0; j < 5; j++)
                C[(size_t)grow * 40 + tx * 5 + j] = __float2half(acc[i][j] * di);
        }
    }
}

// -------------------- CSR aggregation D=128 (fp16 in/out, pure sum) ----------
// out[d] = dinv[d]*( h'[d] + sum_{s in N(d)} h'[s] ) + bias   (+ BN stats)
__global__ void __launch_bounds__(256)
k_agg128(const __half* __restrict__ h, __half* __restrict__ out,
         const float* __restrict__ bias) {
    __shared__ float ssum[128];
    __shared__ float ssq[128];
    int tid  = threadIdx.x;
    int warp = tid >> 5, lane = tid & 31;
    if (tid < 128) { ssum[tid] = 0.f; ssq[tid] = 0.f; }
    __syncthreads();

    int r = blockIdx.x * 8 + warp;
    bool ok = (r < NNODES);       // warp-uniform
    if (ok) {
        const int co = lane * 4;   // this lane's 4 columns
        float4 acc;
        {
            uint2 raw = *(const uint2*)(h + (size_t)r * 128 + co);   // self (already dinv-scaled)
            float2 f0 = __half22float2(*(__half2*)&raw.x);
            float2 f1 = __half22float2(*(__half2*)&raw.y);
            acc.x = f0.x; acc.y = f0.y; acc.z = f1.x; acc.w = f1.y;
        }
        int beg = g_off[r], end = g_off[r + 1];
        int base = beg;
        // full 8-edge chunks: lanes 0..7 fetch indices, broadcast via shfl
        for (; base + 8 <= end; base += 8) {
            int idx = 0;
            if (lane < 8) idx = g_csr[base + lane];
            #pragma unroll
            for (int j = 0; j < 8; j++) {
                int s = __shfl_sync(0xffffffffu, idx, j);
                uint2 raw = *(const uint2*)(h + (size_t)s * 128 + co);
                float2 f0 = __half22float2(*(__half2*)&raw.x);
                float2 f1 = __half22float2(*(__half2*)&raw.y);
                acc.x += f0.x; acc.y += f0.y; acc.z += f1.x; acc.w += f1.y;
            }
        }
        int rem = end - base;
        if (rem > 0) {
            int idx = 0;
            if (lane < rem) idx = g_csr[base + lane];
            for (int j = 0; j < rem; j++) {
                int s = __shfl_sync(0xffffffffu, idx, j);
                uint2 raw = *(const uint2*)(h + (size_t)s * 128 + co);
                float2 f0 = __half22float2(*(__half2*)&raw.x);
                float2 f1 = __half22float2(*(__half2*)&raw.y);
                acc.x += f0.x; acc.y += f0.y; acc.z += f1.x; acc.w += f1.y;
            }
        }
        float dr = g_dinv[r];
        float4 b = *(const float4*)(bias + co);
        float4 v;
        v.x = fmaf(acc.x, dr, b.x);
        v.y = fmaf(acc.y, dr, b.y);
        v.z = fmaf(acc.z, dr, b.z);
        v.w = fmaf(acc.w, dr, b.w);
        // store activation as fp16
        __half2 h0 = __floats2half2_rn(v.x, v.y);
        __half2 h1 = __floats2half2_rn(v.z, v.w);
        uint2 packed; packed.x = *(unsigned*)&h0; packed.y = *(unsigned*)&h1;
        *(uint2*)(out + (size_t)r * 128 + co) = packed;
        // BN stats in fp32
        atomicAdd(&ssum[co + 0], v.x);
        atomicAdd(&ssum[co + 1], v.y);
        atomicAdd(&ssum[co + 2], v.z);
        atomicAdd(&ssum[co + 3], v.w);
        atomicAdd(&ssq[co + 0], v.x * v.x);
        atomicAdd(&ssq[co + 1], v.y * v.y);
        atomicAdd(&ssq[co + 2], v.z * v.z);
        atomicAdd(&ssq[co + 3], v.w * v.w);
    }
    __syncthreads();
    if (tid < 128) {
        atomicAdd(&g_bn[tid], ssum[tid]);
        atomicAdd(&g_bn[128 + tid], ssq[tid]);
    }
}

__global__ void k_bnfin(const float* __restrict__ g, const float* __restrict__ be) {
    int c = threadIdx.x;  // 128 threads
    float inv_n = 1.0f / (float)NNODES;
    float mean = g_bn[c] * inv_n;
    float var  = g_bn[128 + c] * inv_n - mean * mean;
    float sc = g[c] * rsqrtf(var + BNEPS);
    g_bn[256 + c] = sc;
    g_bn[384 + c] = be[c] - mean * sc;
    g_bn[c] = 0.f;           // reset sums for next layer
    g_bn[128 + c] = 0.f;
}

// ------------- CSR aggregation D=40 (fp16 in) + bias + log_softmax -----------
__global__ void __launch_bounds__(256)
k_agg40(const __half* __restrict__ h, float* __restrict__ out,
        const float* __restrict__ bf) {
    int tid  = threadIdx.x;
    int warp = tid >> 5, lane = tid & 31;
    int r = blockIdx.x * 8 + warp;
    if (r >= NNODES) return;     // warp-uniform exit
    bool cok = (lane < 10);      // lanes 0..9 hold the 40 columns as 4 halves each

    const int co = lane * 4;     // half-index within the 40-wide row
    float4 acc = make_float4(0.f, 0.f, 0.f, 0.f);
    if (cok) {
        uint2 raw = *(const uint2*)(h + (size_t)r * 40 + co);    // self (dinv-scaled)
        float2 f0 = __half22float2(*(__half2*)&raw.x);
        float2 f1 = __half22float2(*(__half2*)&raw.y);
        acc = make_float4(f0.x, f0.y, f1.x, f1.y);
    }
    int beg = g_off[r], end = g_off[r + 1];
    int base = beg;
    for (; base + 8 <= end; base += 8) {
        int idx = 0;
        if (lane < 8) idx = g_csr[base + lane];
        #pragma unroll
        for (int j = 0; j < 8; j++) {
            int s = __shfl_sync(0xffffffffu, idx, j);
            if (cok) {
                uint2 raw = *(const uint2*)(h + (size_t)s * 40 + co);
                float2 f0 = __half22float2(*(__half2*)&raw.x);
                float2 f1 = __half22float2(*(__half2*)&raw.y);
                acc.x += f0.x; acc.y += f0.y; acc.z += f1.x; acc.w += f1.y;
            }
        }
    }
    int rem = end - base;
    if (rem > 0) {
        int idx = 0;
        if (lane < rem) idx = g_csr[base + lane];
        for (int j = 0; j < rem; j++) {
            int s = __shfl_sync(0xffffffffu, idx, j);
            if (cok) {
                uint2 raw = *(const uint2*)(h + (size_t)s * 40 + co);
                float2 f0 = __half22float2(*(__half2*)&raw.x);
                float2 f1 = __half22float2(*(__half2*)&raw.y);
                acc.x += f0.x; acc.y += f0.y; acc.z += f1.x; acc.w += f1.y;
            }
        }
    }
    float dr = g_dinv[r];
    float4 v = make_float4(-1e30f, -1e30f, -1e30f, -1e30f);
    if (cok) {
        float4 b = *(const float4*)(bf + co);
        v.x = fmaf(acc.x, dr, b.x);
        v.y = fmaf(acc.y, dr, b.y);
        v.z = fmaf(acc.z, dr, b.z);
        v.w = fmaf(acc.w, dr, b.w);
    }
    // log_softmax over the 40 values (lanes 0..9)
    float m = fmaxf(fmaxf(v.x, v.y), fmaxf(v.z, v.w));
    #pragma unroll
    for (int off = 16; off >= 1; off >>= 1)
        m = fmaxf(m, __shfl_xor_sync(0xffffffffu, m, off));
    float s = 0.f;
    if (cok) s = expf(v.x - m) + expf(v.y - m) + expf(v.z - m) + expf(v.w - m);
    #pragma unroll
    for (int off = 16; off >= 1; off >>= 1)
        s += __shfl_xor_sync(0xffffffffu, s, off);
    float l = m + logf(s);
    if (cok) {
        float4 o = make_float4(v.x - l, v.y - l, v.z - l, v.w - l);
        *(float4*)(out + (size_t)r * 40 + co) = o;
    }
}

// ---------------------------------------------------------------------------
extern "C" void kernel_launch(void* const* d_in, const int* in_sizes, int n_in,
                              void* d_out, int out_size) {
    const float* x   = (const float*)d_in[0];
    const void*  ei  = d_in[1];
    const float* W1  = (const float*)d_in[2];
    const float* b1  = (const float*)d_in[3];
    const float* g1  = (const float*)d_in[4];
    const float* be1 = (const float*)d_in[5];
    const float* W2  = (const float*)d_in[6];
    const float* b2  = (const float*)d_in[7];
    const float* g2  = (const float*)d_in[8];
    const float* be2 = (const float*)d_in[9];
    const float* Wf  = (const float*)d_in[10];
    const float* bf  = (const float*)d_in[11];
    float* out = (float*)d_out;

    __half *ph, *pa;
    float *pbn;
    int   *pcnt;
    cudaGetSymbolAddress((void**)&ph, g_h);
    cudaGetSymbolAddress((void**)&pa, g_a);
    cudaGetSymbolAddress((void**)&pbn, g_bn);
    cudaGetSymbolAddress((void**)&pcnt, g_cnt);
    __half* ph40 = ph;   // reuse g_h for the fp16 [NPAD,40] final-layer features

    const int M = NNODES;
    const int gemmBlocks = (M + 127) / 128;          // 782
    const int edge2Blocks = (NEDGES / 2 + 255) / 256;// 3125
    const int nodeBlocks = (NNODES + 7) / 8;         // 12500
    const int scanBlocks = (NNODES + 1023) / 1024;   // 98

    // ---- setup: CSR build ----
    k_detect<<<1, 256>>>((const long long*)ei);
    k_zero<<<64, 256>>>((float4*)pcnt, NNODES / 4);
    k_zerobn<<<1, 256>>>();
    k_degree<<<edge2Blocks, 256>>>(ei);
    k_scan1<<<scanBlocks, 1024>>>();
    k_scan2<<<1, 128>>>(scanBlocks);
    k_scan3<<<(NNODES + 255) / 256, 256>>>();
    k_scatter<<<edge2Blocks, 256>>>(ei);

    // ---- layer 1 ----
    k_gemm128_h<false, false><<<gemmBlocks, 256>>>(x, W1, ph, nullptr, nullptr, M);
    k_agg128<<<nodeBlocks, 256>>>(ph, pa, b1);
    k_bnfin<<<1, 128>>>(g1, be1);

    // ---- layer 2 ----
    k_gemm128_h<true, true><<<gemmBlocks, 256>>>(pa, W2, ph, pbn + 256, pbn + 384, M);
    k_agg128<<<nodeBlocks, 256>>>(ph, pa, b2);
    k_bnfin<<<1, 128>>>(g2, be2);

    // ---- layer 3 ----
    k_gemm40<<<gemmBlocks, 256>>>(pa, Wf, ph40, pbn + 256, pbn + 384, M);
    k_agg40<<<nodeBlocks, 256>>>(ph40, out, bf);
}

// round 10
// speedup vs baseline: 2.3825x; 1.2556x over previous
#include <cuda_runtime.h>
#include <cuda_fp16.h>
#include <mma.h>
#include <math.h>

using namespace nvcuda;

#define NNODES 100000
#define NEDGES 1600000
#define DH     128
#define DOUT   40
#define BNEPS  1e-5f
#define NPAD   (NNODES + 128)   // padding rows so full-tile stores never escape the buffer

// -------------------- scratch (static device globals) -----------------------
__device__ __align__(16) __half g_h[(size_t)NPAD * DH];    // h' = dinv[row]*(act(A)@W), fp16 gather operand
__device__ __align__(16) __half g_a[(size_t)NPAD * DH];    // activations (fp16, raw pre-BN)
__device__ __align__(16) __half g_w1h[DH * DH];            // W1 in fp16
__device__ __align__(16) __half g_w2h[DH * DH];            // W2 in fp16
__device__ __align__(16) __half g_bnh[256];                // [0:128) half scale, [128:256) half shift
__device__ __align__(16) float  g_dinv[NNODES];            // rsqrt(deg+1)
__device__ __align__(16) int    g_cnt[NNODES];             // in-degree
__device__ __align__(16) int    g_off[NNODES + 1];         // CSR offsets
__device__ __align__(16) int    g_cur[NNODES];             // scatter cursors
__device__ __align__(16) int    g_csr[NEDGES];             // src ids grouped by dst
__device__ __align__(16) int    g_bsum[128];               // scan partials
__device__ __align__(16) int    g_bsumx[128];
__device__ __align__(16) float  g_bn[512];                 // [0:128) sum, [128:256) sumsq, [256:384) scale, [384:512) shift
__device__ int g_is64;

// -------------------- dtype detect ------------------------------------------
__global__ void k_detect(const long long* __restrict__ ei) {
    long long stride = NEDGES / 256;
    long long pos = (long long)threadIdx.x * stride;
    long long v = ei[pos];
    bool bad = ((unsigned long long)v >= (unsigned long long)NNODES);
    unsigned anybad = __ballot_sync(0xffffffffu, bad);
    __shared__ int sbad[8];
    int w = threadIdx.x >> 5;
    if ((threadIdx.x & 31) == 0) sbad[w] = (anybad != 0);
    __syncthreads();
    if (threadIdx.x == 0) {
        int any = 0;
        #pragma unroll
        for (int i = 0; i < 8; i++) any |= sbad[i];
        g_is64 = any ? 0 : 1;
    }
}

// -------------------- W fp32 -> fp16 precompute ------------------------------
__global__ void k_wconv(const float* __restrict__ W1, const float* __restrict__ W2) {
    int i = blockIdx.x * 256 + threadIdx.x;   // 64 blocks x 256 = 16384
    g_w1h[i] = __float2half(W1[i]);
    g_w2h[i] = __float2half(W2[i]);
}

// -------------------- zero helpers ------------------------------------------
__global__ void k_zero(float4* __restrict__ p, int n4) {
    int i = blockIdx.x * blockDim.x + threadIdx.x;
    int stride = gridDim.x * blockDim.x;
    float4 z = make_float4(0.f, 0.f, 0.f, 0.f);
    for (; i < n4; i += stride) p[i] = z;
}
__global__ void k_zerobn() {
    g_bn[threadIdx.x] = 0.f;  // 256 threads: sums+sumsqs
}

// -------------------- degree (2 edges per thread, vector loads) --------------
__global__ void k_degree(const void* __restrict__ ei) {
    int t = blockIdx.x * blockDim.x + threadIdx.x;
    int e = t * 2;
    if (e >= NEDGES) return;
    int d0, d1;
    if (g_is64) {
        longlong2 p = *(const longlong2*)((const long long*)ei + NEDGES + e);
        d0 = (int)p.x; d1 = (int)p.y;
    } else {
        int2 p = *(const int2*)((const int*)ei + NEDGES + e);
        d0 = p.x; d1 = p.y;
    }
    atomicAdd(&g_cnt[d0], 1);
    atomicAdd(&g_cnt[d1], 1);
}

// -------------------- exclusive scan (3 phases; phase3 also builds dinv) -----
__global__ void k_scan1() {
    __shared__ int sh[1024];
    int t = threadIdx.x;
    int i = blockIdx.x * 1024 + t;
    int v = (i < NNODES) ? g_cnt[i] : 0;
    sh[t] = v;
    __syncthreads();
    for (int off = 1; off < 1024; off <<= 1) {
        int x = (t >= off) ? sh[t - off] : 0;
        __syncthreads();
        sh[t] += x;
        __syncthreads();
    }
    if (i < NNODES) g_off[i] = sh[t] - v;   // exclusive
    if (t == 1023) g_bsum[blockIdx.x] = sh[1023];
}

__global__ void k_scan2(int nblocks) {
    __shared__ int sh[128];
    int t = threadIdx.x;           // 128 threads
    int v = (t < nblocks) ? g_bsum[t] : 0;
    sh[t] = v;
    __syncthreads();
    #pragma unroll
    for (int off = 1; off < 128; off <<= 1) {
        int x = (t >= off) ? sh[t - off] : 0;
        __syncthreads();
        sh[t] += x;
        __syncthreads();
    }
    if (t < nblocks) g_bsumx[t] = sh[t] - v;   // exclusive
    if (t == 127) g_off[NNODES] = sh[127];
}

__global__ void k_scan3() {
    int i = blockIdx.x * blockDim.x + threadIdx.x;
    if (i < NNODES) {
        int o = g_off[i] + g_bsumx[i >> 10];
        g_off[i] = o;
        g_cur[i] = o;
        g_dinv[i] = rsqrtf((float)g_cnt[i] + 1.0f);
    }
}

// -------------------- scatter edges into CSR (2 edges per thread) ------------
__global__ void k_scatter(const void* __restrict__ ei) {
    int t = blockIdx.x * blockDim.x + threadIdx.x;
    int e = t * 2;
    if (e >= NEDGES) return;
    int s0, d0, s1, d1;
    if (g_is64) {
        const long long* p = (const long long*)ei;
        longlong2 sp = *(const longlong2*)(p + e);
        longlong2 dp = *(const longlong2*)(p + NEDGES + e);
        s0 = (int)sp.x; s1 = (int)sp.y; d0 = (int)dp.x; d1 = (int)dp.y;
    } else {
        const int* p = (const int*)ei;
        int2 sp = *(const int2*)(p + e);
        int2 dp = *(const int2*)(p + NEDGES + e);
        s0 = sp.x; s1 = sp.y; d0 = dp.x; d1 = dp.y;
    }
    g_csr[atomicAdd(&g_cur[d0], 1)] = s0;
    g_csr[atomicAdd(&g_cur[d1], 1)] = s1;
}

// -------------------- fp16 HMMA GEMM  C[M,128] = dinv[row]*(act(A)@W) --------
// Block: 128x128 tile, 8 warps as 4(M) x 2(N); warp 32x64 = 2x4 m16n16k16 tiles.
// W pre-converted to fp16. BN+ReLU applied in fp16 (g_bnh). Direct-register epilogue.
template <bool A_HALF, bool APPLY_BN>
__global__ void __launch_bounds__(256)
k_gemm128_h(const void* __restrict__ Av, const __half* __restrict__ Wh,
            __half* __restrict__ C, int M) {
    __shared__ __half As[128][40];    // 128 rows x 32 k (pad 8 halves; conflict-free ldmatrix)
    __shared__ __half Bs[32][136];    // 32 k x 128 n   (pad 8)

    const int tid   = threadIdx.x;
    const int warp  = tid >> 5;
    const int lane  = tid & 31;
    const int warpM = warp >> 1;     // 0..3
    const int warpN = warp & 1;      // 0..1
    const int blockRow = blockIdx.x * 128;

    wmma::fragment<wmma::accumulator, 16, 16, 16, float> acc[2][4];
    #pragma unroll
    for (int i = 0; i < 2; i++)
        #pragma unroll
        for (int j = 0; j < 4; j++)
            wmma::fill_fragment(acc[i][j], 0.0f);

    for (int kt = 0; kt < 4; kt++) {
        // ---- A tile: 128 rows x 32 k (half), BN+ReLU fused in fp16
        #pragma unroll
        for (int it = 0; it < 4; it++) {
            int idx = tid + it * 256;            // 0..1023
            int r   = idx >> 3;                  // 0..127
            int c4  = idx & 7;                   // 4-half group
            int grow = blockRow + r;
            uint2 packed;
            if (A_HALF) {
                // g_a has NPAD rows: no row guard needed; padding rows produce
                // garbage that lands only in C's padding rows (never read).
                uint2 raw = *(const uint2*)((const __half*)Av + (size_t)grow * 128 + kt * 32 + c4 * 4);
                if (APPLY_BN) {
                    int c = kt * 32 + c4 * 4;
                    __half2 sc0 = *(const __half2*)&g_bnh[c];
                    __half2 sc1 = *(const __half2*)&g_bnh[c + 2];
                    __half2 sh0 = *(const __half2*)&g_bnh[128 + c];
                    __half2 sh1 = *(const __half2*)&g_bnh[128 + c + 2];
                    __half2 z = __float2half2_rn(0.f);
                    __half2 v0 = __hmax2(__hfma2(*(__half2*)&raw.x, sc0, sh0), z);
                    __half2 v1 = __hmax2(__hfma2(*(__half2*)&raw.y, sc1, sh1), z);
                    packed.x = *(unsigned*)&v0; packed.y = *(unsigned*)&v1;
                } else {
                    packed = raw;
                }
            } else {
                float4 v = make_float4(0.f, 0.f, 0.f, 0.f);
                if (grow < M) v = *(const float4*)((const float*)Av + (size_t)grow * 128 + kt * 32 + c4 * 4);
                __half2 h0 = __floats2half2_rn(v.x, v.y);
                __half2 h1 = __floats2half2_rn(v.z, v.w);
                packed.x = *(unsigned*)&h0; packed.y = *(unsigned*)&h1;
            }
            *(uint2*)&As[r][c4 * 4] = packed;
        }
        // ---- B tile: 32 k x 128 n, raw fp16 copy (no conversion)
        #pragma unroll
        for (int it = 0; it < 4; it++) {
            int idx = tid + it * 256;            // 0..1023
            int r   = idx >> 5;                  // 0..31
            int c4  = idx & 31;                  // 0..31
            *(uint2*)&Bs[r][c4 * 4] = *(const uint2*)(Wh + (size_t)(kt * 32 + r) * 128 + c4 * 4);
        }
        __syncthreads();

        #pragma unroll
        for (int ks = 0; ks < 2; ks++) {
            wmma::fragment<wmma::matrix_a, 16, 16, 16, __half, wmma::row_major> af[2];
            wmma::fragment<wmma::matrix_b, 16, 16, 16, __half, wmma::row_major> bfr[4];
            #pragma unroll
            for (int i = 0; i < 2; i++)
                wmma::load_matrix_sync(af[i], &As[warpM * 32 + i * 16][ks * 16], 40);
            #pragma unroll
            for (int j = 0; j < 4; j++)
                wmma::load_matrix_sync(bfr[j], &Bs[ks * 16][warpN * 64 + j * 16], 136);
            #pragma unroll
            for (int i = 0; i < 2; i++)
                #pragma unroll
                for (int j = 0; j < 4; j++)
                    wmma::mma_sync(acc[i][j], af[i], bfr[j], acc[i][j]);
        }
        __syncthreads();
    }

    // ---- direct-register epilogue: fp32 acc * dinv[row] -> fp16 C
    // m16n16k16 fp32 accumulator layout (sm_80+):
    //   x[0],x[1] -> (gid,   tig*2 .. +1)    x[2],x[3] -> (gid+8, tig*2 .. +1)
    //   x[4],x[5] -> (gid,   tig*2+8 ..)     x[6],x[7] -> (gid+8, tig*2+8 ..)
    const int gid = lane >> 2;     // 0..7
    const int tig = lane & 3;      // 0..3
    #pragma unroll
    for (int i = 0; i < 2; i++) {
        int r0 = blockRow + warpM * 32 + i * 16 + gid;
        int r1 = r0 + 8;
        float d0 = (r0 < M) ? g_dinv[r0] : 0.f;
        float d1 = (r1 < M) ? g_dinv[r1] : 0.f;
        #pragma unroll
        for (int j = 0; j < 4; j++) {
            int c0 = warpN * 64 + j * 16 + tig * 2;
            __half2 p00 = __floats2half2_rn(acc[i][j].x[0] * d0, acc[i][j].x[1] * d0);
            __half2 p10 = __floats2half2_rn(acc[i][j].x[2] * d1, acc[i][j].x[3] * d1);
            __half2 p01 = __floats2half2_rn(acc[i][j].x[4] * d0, acc[i][j].x[5] * d0);
            __half2 p11 = __floats2half2_rn(acc[i][j].x[6] * d1, acc[i][j].x[7] * d1);
            *(__half2*)(C + (size_t)r0 * 128 + c0)     = p00;
            *(__half2*)(C + (size_t)r1 * 128 + c0)     = p10;
            *(__half2*)(C + (size_t)r0 * 128 + c0 + 8) = p01;
            *(__half2*)(C + (size_t)r1 * 128 + c0 + 8) = p11;
        }
    }
}

// -------------- SGEMM  C[M,40] = dinv[row]*(act(A)@W)  (A fp16, fp16 out) ----
__global__ void __launch_bounds__(256)
k_gemm40(const __half* __restrict__ A, const float* __restrict__ W,
         __half* __restrict__ C,
         const float* __restrict__ scale, const float* __restrict__ shift, int M) {
    __shared__ float As[16][132];
    __shared__ float Bs[16][40];

    const int tid = threadIdx.x;
    const int tx = tid & 7;
    const int ty = tid >> 3;
    const int blockRow = blockIdx.x * 128;

    float acc[4][5];
    #pragma unroll
    for (int i = 0; i < 4; i++)
        #pragma unroll
        for (int j = 0; j < 5; j++) acc[i][j] = 0.f;

    for (int k0 = 0; k0 < 128; k0 += 16) {
        #pragma unroll
        for (int it = 0; it < 2; it++) {
            int idx = tid + it * 256;
            int r   = idx >> 2;
            int c4  = idx & 3;
            int grow = blockRow + r;
            float4 v = make_float4(0.f, 0.f, 0.f, 0.f);
            if (grow < M) {
                uint2 raw = *(const uint2*)(A + (size_t)grow * 128 + k0 + c4 * 4);
                float2 f0 = __half22float2(*(__half2*)&raw.x);
                float2 f1 = __half22float2(*(__half2*)&raw.y);
                v = make_float4(f0.x, f0.y, f1.x, f1.y);
            }
            int c = k0 + c4 * 4;
            v.x = fmaxf(fmaf(v.x, scale[c + 0], shift[c + 0]), 0.f);
            v.y = fmaxf(fmaf(v.y, scale[c + 1], shift[c + 1]), 0.f);
            v.z = fmaxf(fmaf(v.z, scale[c + 2], shift[c + 2]), 0.f);
            v.w = fmaxf(fmaf(v.w, scale[c + 3], shift[c + 3]), 0.f);
            As[c4 * 4 + 0][r] = v.x;
            As[c4 * 4 + 1][r] = v.y;
            As[c4 * 4 + 2][r] = v.z;
            As[c4 * 4 + 3][r] = v.w;
        }
        for (int idx = tid; idx < 16 * 40; idx += 256) {
            int r = idx / 40, c = idx % 40;
            Bs[r][c] = W[(size_t)(k0 + r) * 40 + c];
        }
        __syncthreads();

        #pragma unroll
        for (int k = 0; k < 16; k++) {
            float a[4], b[5];
            *(float4*)a = *(const float4*)&As[k][ty * 4];
            #pragma unroll
            for (int j = 0; j < 5; j++) b[j] = Bs[k][tx * 5 + j];
            #pragma unroll
            for (int i = 0; i < 4; i++)
                #pragma unroll
                for (int j = 0; j < 5; j++)
                    acc[i][j] = fmaf(a[i], b[j], acc[i][j]);
        }
        __syncthreads();
    }

    #pragma unroll
    for (int i = 0; i < 4; i++) {
        int grow = blockRow + ty * 4 + i;
        if (grow < M) {
            float di = g_dinv[grow];
            #pragma unroll
            for (int j = 0; j < 5; j++)
                C[(size_t)grow * 40 + tx * 5 + j] = __float2half(acc[i][j] * di);
        }
    }
}

// -------------------- CSR aggregation D=128 (fp16 in/out, pure sum) ----------
// out[d] = dinv[d]*( h'[d] + sum_{s in N(d)} h'[s] ) + bias   (+ BN stats)
__global__ void __launch_bounds__(256)
k_agg128(const __half* __restrict__ h, __half* __restrict__ out,
         const float* __restrict__ bias) {
    __shared__ float ssum[128];
    __shared__ float ssq[128];
    int tid  = threadIdx.x;
    int warp = tid >> 5, lane = tid & 31;
    if (tid < 128) { ssum[tid] = 0.f; ssq[tid] = 0.f; }
    __syncthreads();

    int r = blockIdx.x * 8 + warp;
    bool ok = (r < NNODES);       // warp-uniform
    if (ok) {
        const int co = lane * 4;   // this lane's 4 columns
        float4 acc;
        {
            uint2 raw = *(const uint2*)(h + (size_t)r * 128 + co);   // self (already dinv-scaled)
            float2 f0 = __half22float2(*(__half2*)&raw.x);
            float2 f1 = __half22float2(*(__half2*)&raw.y);
            acc.x = f0.x; acc.y = f0.y; acc.z = f1.x; acc.w = f1.y;
        }
        int beg = g_off[r], end = g_off[r + 1];
        int base = beg;
        for (; base + 8 <= end; base += 8) {
            int idx = 0;
            if (lane < 8) idx = g_csr[base + lane];
            #pragma unroll
            for (int j = 0; j < 8; j++) {
                int s = __shfl_sync(0xffffffffu, idx, j);
                uint2 raw = *(const uint2*)(h + (size_t)s * 128 + co);
                float2 f0 = __half22float2(*(__half2*)&raw.x);
                float2 f1 = __half22float2(*(__half2*)&raw.y);
                acc.x += f0.x; acc.y += f0.y; acc.z += f1.x; acc.w += f1.y;
            }
        }
        int rem = end - base;
        if (rem > 0) {
            int idx = 0;
            if (lane < rem) idx = g_csr[base + lane];
            for (int j = 0; j < rem; j++) {
                int s = __shfl_sync(0xffffffffu, idx, j);
                uint2 raw = *(const uint2*)(h + (size_t)s * 128 + co);
                float2 f0 = __half22float2(*(__half2*)&raw.x);
                float2 f1 = __half22float2(*(__half2*)&raw.y);
                acc.x += f0.x; acc.y += f0.y; acc.z += f1.x; acc.w += f1.y;
            }
        }
        float dr = g_dinv[r];
        float4 b = *(const float4*)(bias + co);
        float4 v;
        v.x = fmaf(acc.x, dr, b.x);
        v.y = fmaf(acc.y, dr, b.y);
        v.z = fmaf(acc.z, dr, b.z);
        v.w = fmaf(acc.w, dr, b.w);
        __half2 h0 = __floats2half2_rn(v.x, v.y);
        __half2 h1 = __floats2half2_rn(v.z, v.w);
        uint2 packed; packed.x = *(unsigned*)&h0; packed.y = *(unsigned*)&h1;
        *(uint2*)(out + (size_t)r * 128 + co) = packed;
        atomicAdd(&ssum[co + 0], v.x);
        atomicAdd(&ssum[co + 1], v.y);
        atomicAdd(&ssum[co + 2], v.z);
        atomicAdd(&ssum[co + 3], v.w);
        atomicAdd(&ssq[co + 0], v.x * v.x);
        atomicAdd(&ssq[co + 1], v.y * v.y);
        atomicAdd(&ssq[co + 2], v.z * v.z);
        atomicAdd(&ssq[co + 3], v.w * v.w);
    }
    __syncthreads();
    if (tid < 128) {
        atomicAdd(&g_bn[tid], ssum[tid]);
        atomicAdd(&g_bn[128 + tid], ssq[tid]);
    }
}

__global__ void k_bnfin(const float* __restrict__ g, const float* __restrict__ be) {
    int c = threadIdx.x;  // 128 threads
    float inv_n = 1.0f / (float)NNODES;
    float mean = g_bn[c] * inv_n;
    float var  = g_bn[128 + c] * inv_n - mean * mean;
    float sc = g[c] * rsqrtf(var + BNEPS);
    float sh = be[c] - mean * sc;
    g_bn[256 + c] = sc;
    g_bn[384 + c] = sh;
    g_bnh[c]       = __float2half(sc);   // half versions for the HMMA GEMM
    g_bnh[128 + c] = __float2half(sh);
    g_bn[c] = 0.f;           // reset sums for next layer
    g_bn[128 + c] = 0.f;
}

// ------------- CSR aggregation D=40 (fp16 in) + bias + log_softmax -----------
__global__ void __launch_bounds__(256)
k_agg40(const __half* __restrict__ h, float* __restrict__ out,
        const float* __restrict__ bf) {
    int tid  = threadIdx.x;
    int warp = tid >> 5, lane = tid & 31;
    int r = blockIdx.x * 8 + warp;
    if (r >= NNODES) return;     // warp-uniform exit
    bool cok = (lane < 10);      // lanes 0..9 hold the 40 columns as 4 halves each

    const int co = lane * 4;     // half-index within the 40-wide row
    float4 acc = make_float4(0.f, 0.f, 0.f, 0.f);
    if (cok) {
        uint2 raw = *(const uint2*)(h + (size_t)r * 40 + co);    // self (dinv-scaled)
        float2 f0 = __half22float2(*(__half2*)&raw.x);
        float2 f1 = __half22float2(*(__half2*)&raw.y);
        acc = make_float4(f0.x, f0.y, f1.x, f1.y);
    }
    int beg = g_off[r], end = g_off[r + 1];
    int base = beg;
    for (; base + 8 <= end; base += 8) {
        int idx = 0;
        if (lane < 8) idx = g_csr[base + lane];
        #pragma unroll
        for (int j = 0; j < 8; j++) {
            int s = __shfl_sync(0xffffffffu, idx, j);
            if (cok) {
                uint2 raw = *(const uint2*)(h + (size_t)s * 40 + co);
                float2 f0 = __half22float2(*(__half2*)&raw.x);
                float2 f1 = __half22float2(*(__half2*)&raw.y);
                acc.x += f0.x; acc.y += f0.y; acc.z += f1.x; acc.w += f1.y;
            }
        }
    }
    int rem = end - base;
    if (rem > 0) {
        int idx = 0;
        if (lane < rem) idx = g_csr[base + lane];
        for (int j = 0; j < rem; j++) {
            int s = __shfl_sync(0xffffffffu, idx, j);
            if (cok) {
                uint2 raw = *(const uint2*)(h + (size_t)s * 40 + co);
                float2 f0 = __half22float2(*(__half2*)&raw.x);
                float2 f1 = __half22float2(*(__half2*)&raw.y);
                acc.x += f0.x; acc.y += f0.y; acc.z += f1.x; acc.w += f1.y;
            }
        }
    }
    float dr = g_dinv[r];
    float4 v = make_float4(-1e30f, -1e30f, -1e30f, -1e30f);
    if (cok) {
        float4 b = *(const float4*)(bf + co);
        v.x = fmaf(acc.x, dr, b.x);
        v.y = fmaf(acc.y, dr, b.y);
        v.z = fmaf(acc.z, dr, b.z);
        v.w = fmaf(acc.w, dr, b.w);
    }
    // log_softmax over the 40 values (lanes 0..9)
    float m = fmaxf(fmaxf(v.x, v.y), fmaxf(v.z, v.w));
    #pragma unroll
    for (int off = 16; off >= 1; off >>= 1)
        m = fmaxf(m, __shfl_xor_sync(0xffffffffu, m, off));
    float s = 0.f;
    if (cok) s = expf(v.x - m) + expf(v.y - m) + expf(v.z - m) + expf(v.w - m);
    #pragma unroll
    for (int off = 16; off >= 1; off >>= 1)
        s += __shfl_xor_sync(0xffffffffu, s, off);
    float l = m + logf(s);
    if (cok) {
        float4 o = make_float4(v.x - l, v.y - l, v.z - l, v.w - l);
        *(float4*)(out + (size_t)r * 40 + co) = o;
    }
}

// ---------------------------------------------------------------------------
extern "C" void kernel_launch(void* const* d_in, const int* in_sizes, int n_in,
                              void* d_out, int out_size) {
    const float* x   = (const float*)d_in[0];
    const void*  ei  = d_in[1];
    const float* W1  = (const float*)d_in[2];
    const float* b1  = (const float*)d_in[3];
    const float* g1  = (const float*)d_in[4];
    const float* be1 = (const float*)d_in[5];
    const float* W2  = (const float*)d_in[6];
    const float* b2  = (const float*)d_in[7];
    const float* g2  = (const float*)d_in[8];
    const float* be2 = (const float*)d_in[9];
    const float* Wf  = (const float*)d_in[10];
    const float* bf  = (const float*)d_in[11];
    float* out = (float*)d_out;

    __half *ph, *pa, *pw1h, *pw2h;
    float *pbn;
    int   *pcnt;
    cudaGetSymbolAddress((void**)&ph, g_h);
    cudaGetSymbolAddress((void**)&pa, g_a);
    cudaGetSymbolAddress((void**)&pw1h, g_w1h);
    cudaGetSymbolAddress((void**)&pw2h, g_w2h);
    cudaGetSymbolAddress((void**)&pbn, g_bn);
    cudaGetSymbolAddress((void**)&pcnt, g_cnt);
    __half* ph40 = ph;   // reuse g_h for the fp16 [NPAD,40] final-layer features

    const int M = NNODES;
    const int gemmBlocks = (M + 127) / 128;          // 782
    const int edge2Blocks = (NEDGES / 2 + 255) / 256;// 3125
    const int nodeBlocks = (NNODES + 7) / 8;         // 12500
    const int scanBlocks = (NNODES + 1023) / 1024;   // 98

    // ---- setup: CSR build + W conversion ----
    k_detect<<<1, 256>>>((const long long*)ei);
    k_wconv<<<64, 256>>>(W1, W2);
    k_zero<<<64, 256>>>((float4*)pcnt, NNODES / 4);
    k_zerobn<<<1, 256>>>();
    k_degree<<<edge2Blocks, 256>>>(ei);
    k_scan1<<<scanBlocks, 1024>>>();
    k_scan2<<<1, 128>>>(scanBlocks);
    k_scan3<<<(NNODES + 255) / 256, 256>>>();
    k_scatter<<<edge2Blocks, 256>>>(ei);

    // ---- layer 1 ----
    k_gemm128_h<false, false><<<gemmBlocks, 256>>>(x, pw1h, ph, M);
    k_agg128<<<nodeBlocks, 256>>>(ph, pa, b1);
    k_bnfin<<<1, 128>>>(g1, be1);

    // ---- layer 2 ----
    k_gemm128_h<true, true><<<gemmBlocks, 256>>>(pa, pw2h, ph, M);
    k_agg128<<<nodeBlocks, 256>>>(ph, pa, b2);
    k_bnfin<<<1, 128>>>(g2, be2);

    // ---- layer 3 ----
    k_gemm40<<<gemmBlocks, 256>>>(pa, Wf, ph40, pbn + 256, pbn + 384, M);
    k_agg40<<<nodeBlocks, 256>>>(ph40, out, bf);
}